// round 9
// baseline (speedup 1.0000x reference)
#include <cuda_runtime.h>
#include <cuda_bf16.h>
#include <math.h>
#include <stdint.h>

#define HW 65536

// ---------------------------------------------------------------------------
// Scratch (no allocations allowed)
// ---------------------------------------------------------------------------
__device__ float          g_f32[8ULL * 65536 * 32];    //  64 MB NHWC fp32 conv outputs
__device__ __nv_bfloat16  g_hi [8ULL * 65536 * 128];   // 128 MB NHWC bf16 hi
__device__ __nv_bfloat16  g_lo [8ULL * 65536 * 128];   // 128 MB NHWC bf16 lo
__device__ __align__(16) char g_wb[334848];            // prepped B (padded row-major, hi|lo)
// conv1: hi@0      lo@18944   (BSTR=592,  32 rows)
// conv2: hi@37888  lo@112128  (BSTR=2320, 32 rows)
// conv3: hi@186368 lo@260608

// ---------------------------------------------------------------------------
__device__ __forceinline__ uint32_t smem_u32(const void* p) {
    uint32_t a;
    asm("{ .reg .u64 t; cvta.to.shared.u64 t, %1; cvt.u32.u64 %0, t; }" : "=r"(a) : "l"(p));
    return a;
}
__device__ __forceinline__ void ldm4(uint32_t* r, uint32_t a) {
    asm volatile("ldmatrix.sync.aligned.m8n8.x4.shared.b16 {%0,%1,%2,%3}, [%4];"
                 : "=r"(r[0]), "=r"(r[1]), "=r"(r[2]), "=r"(r[3]) : "r"(a));
}
__device__ __forceinline__ void mma16816(float* c, const uint32_t* a, uint32_t b0, uint32_t b1) {
    asm volatile("mma.sync.aligned.m16n8k16.row.col.f32.bf16.bf16.f32 "
        "{%0,%1,%2,%3}, {%4,%5,%6,%7}, {%8,%9}, {%0,%1,%2,%3};"
        : "+f"(c[0]), "+f"(c[1]), "+f"(c[2]), "+f"(c[3])
        : "r"(a[0]), "r"(a[1]), "r"(a[2]), "r"(a[3]), "r"(b0), "r"(b1));
}
__device__ __forceinline__ void cp16(uint32_t saddr, const void* gaddr, int sz) {
    asm volatile("cp.async.cg.shared.global [%0], [%1], 16, %2;"
                 :: "r"(saddr), "l"(gaddr), "r"(sz));
}
__device__ __forceinline__ void cp_commit_wait() {
    asm volatile("cp.async.commit_group;");
    asm volatile("cp.async.wait_group 0;");
}

// ---------------------------------------------------------------------------
// Weight prep: fp32 [32][CIN][3][3] -> bf16 hi/lo padded row-major B images.
// ---------------------------------------------------------------------------
__global__ void prep_w(const float* __restrict__ w, char* __restrict__ bhi,
                       char* __restrict__ blo, int CIN)
{
    int K = 9 * CIN, KP = K + 8, BSTR = K * 2 + 16;
    int idx = blockIdx.x * 256 + threadIdx.x;
    if (idx >= 32 * KP) return;
    int n = idx / KP, k = idx - n * KP;
    float v = 0.f;
    if (k < K) {
        int dyi = k / (3 * CIN);
        int r   = k - dyi * 3 * CIN;
        int dxi = r / CIN;
        int c   = r - dxi * CIN;
        v = w[(n * CIN + c) * 9 + dyi * 3 + dxi];
    }
    __nv_bfloat16 hi = __float2bfloat16(v);
    __nv_bfloat16 lo = __float2bfloat16(v - __bfloat162float(hi));
    int o = n * BSTR + k * 2;
    *(__nv_bfloat16*)(bhi + o) = hi;
    *(__nv_bfloat16*)(blo + o) = lo;
}

// ---------------------------------------------------------------------------
// x (NCHW fp32) -> NHWC bf16 hi/lo (32 ch)
// ---------------------------------------------------------------------------
__global__ __launch_bounds__(256)
void transpose_x(const float* __restrict__ x, __nv_bfloat16* __restrict__ ohi,
                 __nv_bfloat16* __restrict__ olo)
{
    __shared__ float t[32][33];
    int b = blockIdx.y;
    int p0 = blockIdx.x * 32;
    int lane = threadIdx.x & 31, grp = threadIdx.x >> 5;
#pragma unroll
    for (int i = 0; i < 4; i++) {
        int c = grp + i * 8;
        t[c][lane] = x[((size_t)b * 32 + c) * HW + p0 + lane];
    }
    __syncthreads();
#pragma unroll
    for (int i = 0; i < 4; i++) {
        int p = grp + i * 8;
        float v = t[lane][p];
        __nv_bfloat16 hi = __float2bfloat16(v);
        __nv_bfloat16 lo = __float2bfloat16(v - __bfloat162float(hi));
        size_t o = ((size_t)b * HW + p0 + p) * 32 + lane;
        ohi[o] = hi; olo[o] = lo;
    }
}

// ---------------------------------------------------------------------------
// HMMA implicit-GEMM 3x3 conv, 4 output rows per CTA, 512 threads (16 warps).
// Warp w: m-tile = w>>1 (16 px), n-half = w&1 (16 couts).  acc[4][8].
// A staged per input row via cp.async; B hi+lo via ldmatrix from smem.
// Split-3: acc += Ahi*Bhi + Alo*Bhi + Ahi*Blo (fp32 accumulators).
// ---------------------------------------------------------------------------
template<int CIN, bool FUSE>
__global__ __launch_bounds__(512, 1)
void conv_mma(const __nv_bfloat16* __restrict__ ahi, const __nv_bfloat16* __restrict__ alo,
              const char* __restrict__ wb, const float* __restrict__ wout,
              float* __restrict__ out)
{
    constexpr int K     = 9 * CIN;
    constexpr int ASTR  = CIN * 2 + 16;        // A row stride (bytes)
    constexpr int BSTR  = K * 2 + 16;          // B row stride (bytes)
    constexpr int BBYT  = 32 * BSTR;           // one split's B image
    constexpr int V4    = CIN / 8;             // uint4 per pixel-row
    constexpr int ABYT  = 130 * ASTR;          // one input row (one split)

    extern __shared__ __align__(16) char smem[];
    __shared__ float s_red[2][128];            // FUSE cross-half reduction
    // [Bhi BBYT][Blo BBYT][Ahi ABYT][Alo ABYT]
    const int tid  = threadIdx.x;
    const int lane = tid & 31;
    const int wid  = tid >> 5;                 // 0..15
    const int nh   = wid & 1;                  // n-half
    const int w0   = blockIdx.x << 7;
    const int h0   = blockIdx.y << 2;          // first of 4 output rows
    const int b    = blockIdx.z;

    const uint32_t s0   = smem_u32(smem);
    const uint32_t sBhi = s0;
    const uint32_t sBlo = s0 + BBYT;
    const uint32_t sAhi = s0 + 2 * BBYT;
    const uint32_t sAlo = sAhi + ABYT;

    // copy B (hi|lo contiguous) into smem via cp.async
    {
        const int n4 = 2 * BBYT / 16;
        for (int i = tid; i < n4; i += 512)
            cp16(s0 + i * 16, wb + i * 16, 16);
        cp_commit_wait();
    }

    const int m0 = (wid >> 1) << 4;            // 16-px m tile
    const uint32_t aRowOff = (uint32_t)(lane & 15) * ASTR + ((lane & 16) ? 16u : 0u);
    // B ldmatrix (n16 x k16 for this warp's n-half)
    const uint32_t bLM = (uint32_t)((lane & 7) + ((lane & 16) ? 8 : 0) + nh * 16) * BSTR
                       + (uint32_t)((lane >> 3) & 1) * 16;

    float acc[4][8];
#pragma unroll
    for (int r = 0; r < 4; r++)
#pragma unroll
        for (int i = 0; i < 8; i++) acc[r][i] = 0.f;

    for (int s = 0; s < 6; s++) {
        const int ir = h0 - 1 + s;                 // input row
        __syncthreads();
        if ((unsigned)ir < 256u) {
            // stage A row [130 px][CIN] hi+lo with zero-fill w-halo via cp.async
            const size_t rowbase = ((size_t)b * HW + (size_t)ir * 256);
            for (int i = tid; i < 130 * V4; i += 512) {
                int px = i / V4, v = i - px * V4;
                int w  = w0 - 1 + px;
                int ok = ((unsigned)w < 256u);
                int wc = ok ? w : 0;
                uint32_t d = (uint32_t)(px * ASTR + v * 16);
                cp16(sAhi + d, (const char*)(ahi + (rowbase + wc) * CIN) + v * 16, ok ? 16 : 0);
                cp16(sAlo + d, (const char*)(alo + (rowbase + wc) * CIN) + v * 16, ok ? 16 : 0);
            }
            cp_commit_wait();
        }
        __syncthreads();
        if ((unsigned)ir >= 256u) continue;

#pragma unroll
        for (int r = 0; r < 4; r++) {
            const int dy = s - r;
            if (dy < 0 || dy > 2) continue;
#pragma unroll
            for (int dx = 0; dx < 3; dx++) {
#pragma unroll
                for (int kc = 0; kc < CIN / 16; kc++) {
                    uint32_t ah[4], al[4];
                    const uint32_t abase = (uint32_t)(m0 + dx) * ASTR + kc * 32 + aRowOff;
                    ldm4(ah, sAhi + abase);
                    ldm4(al, sAlo + abase);
                    const uint32_t kb = (uint32_t)(dy * 3 * CIN + dx * CIN + kc * 16) * 2;
                    uint32_t bh[4], bl[4];
                    ldm4(bh, sBhi + bLM + kb);       // this warp's n16 (hi)
                    ldm4(bl, sBlo + bLM + kb);       // this warp's n16 (lo)
                    float* a0 = acc[r];
                    mma16816(a0 + 0, ah, bh[0], bh[1]);
                    mma16816(a0 + 4, ah, bh[2], bh[3]);
                    mma16816(a0 + 0, al, bh[0], bh[1]);
                    mma16816(a0 + 4, al, bh[2], bh[3]);
                    mma16816(a0 + 0, ah, bl[0], bl[1]);
                    mma16816(a0 + 4, ah, bl[2], bl[3]);
                }
            }
        }
    }

    // epilogue (4 rows)
    const int prow = m0 + (lane >> 2);
#pragma unroll
    for (int r = 0; r < 4; r++) {
        const int h = h0 + r;
        if (!FUSE) {
            float* ob = out + ((size_t)b * HW + (size_t)h * 256 + w0) * 32;
#pragma unroll
            for (int nt = 0; nt < 2; nt++) {
                int ch = nh * 16 + nt * 8 + (lane & 3) * 2;
                *(float2*)(ob + (size_t)prow * 32 + ch)       = make_float2(acc[r][nt * 4 + 0], acc[r][nt * 4 + 1]);
                *(float2*)(ob + (size_t)(prow + 8) * 32 + ch) = make_float2(acc[r][nt * 4 + 2], acc[r][nt * 4 + 3]);
            }
        } else {
            float s0v = 0.f, s1v = 0.f;
#pragma unroll
            for (int nt = 0; nt < 2; nt++) {
                int ch = nh * 16 + nt * 8 + (lane & 3) * 2;
                float wa = __ldg(&wout[ch]), wb2 = __ldg(&wout[ch + 1]);
                s0v += fmaxf(acc[r][nt * 4 + 0], 0.f) * wa + fmaxf(acc[r][nt * 4 + 1], 0.f) * wb2;
                s1v += fmaxf(acc[r][nt * 4 + 2], 0.f) * wa + fmaxf(acc[r][nt * 4 + 3], 0.f) * wb2;
            }
            s0v += __shfl_xor_sync(0xffffffffu, s0v, 1);
            s0v += __shfl_xor_sync(0xffffffffu, s0v, 2);
            s1v += __shfl_xor_sync(0xffffffffu, s1v, 1);
            s1v += __shfl_xor_sync(0xffffffffu, s1v, 2);
            if ((lane & 3) == 0) {
                s_red[nh][prow]     = s0v;
                s_red[nh][prow + 8] = s1v;
            }
            __syncthreads();
            if (tid < 128) {
                float sv = s_red[0][tid] + s_red[1][tid];
                out[(size_t)b * HW + (size_t)h * 256 + w0 + tid] = 1.0f / (1.0f + expf(-sv));
            }
            __syncthreads();
        }
    }
}

// ---------------------------------------------------------------------------
// IRNN: all 4 directional scans in ONE kernel (blockIdx.y = direction).
// ---------------------------------------------------------------------------
template<bool REV>
__device__ __forceinline__
void scan_h_body(const float* __restrict__ in, __nv_bfloat16* __restrict__ ohi,
                 __nv_bfloat16* __restrict__ olo, float wc, float bc, int c, int ch_off)
{
    int t = blockIdx.x * 256 + threadIdx.x;      // over B*W*C = 65536
    int w = (t >> 5) & 255, b = t >> 13;
    const float* ip = in + (size_t)b * HW * 32 + (size_t)w * 32 + c;
    size_t ob = (size_t)b * HW * 128 + (size_t)w * 128 + ch_off + c;

    float hst = REV ? ip[(size_t)255 * 8192] : ip[0];
    {
        size_t o = ob + (size_t)(REV ? 255 : 0) * 32768;
        __nv_bfloat16 hi = __float2bfloat16(hst);
        ohi[o] = hi; olo[o] = __float2bfloat16(hst - __bfloat162float(hi));
    }
#pragma unroll 8
    for (int i = 1; i < 256; i++) {
        int y = REV ? (255 - i) : i;
        hst = fmaxf(wc * hst + bc + ip[(size_t)y * 8192], 0.f);
        size_t o = ob + (size_t)y * 32768;
        __nv_bfloat16 hi = __float2bfloat16(hst);
        ohi[o] = hi; olo[o] = __float2bfloat16(hst - __bfloat162float(hi));
    }
}

template<bool REV>
__device__ __forceinline__
void scan_w_body(const float* __restrict__ in, __nv_bfloat16* __restrict__ ohi,
                 __nv_bfloat16* __restrict__ olo, float wc, float bc, int c, int ch_off)
{
    int t = blockIdx.x * 256 + threadIdx.x;      // over B*H*C = 65536
    int h = (t >> 5) & 255, b = t >> 13;
    const float* ip = in + (size_t)b * HW * 32 + (size_t)h * 8192 + c;
    size_t ob = (size_t)b * HW * 128 + (size_t)h * 32768 + ch_off + c;

    float hst = REV ? ip[255 * 32] : ip[0];
    {
        size_t o = ob + (size_t)(REV ? 255 : 0) * 128;
        __nv_bfloat16 hi = __float2bfloat16(hst);
        ohi[o] = hi; olo[o] = __float2bfloat16(hst - __bfloat162float(hi));
    }
#pragma unroll 8
    for (int i = 1; i < 256; i++) {
        int w = REV ? (255 - i) : i;
        hst = fmaxf(wc * hst + bc + ip[w * 32], 0.f);
        size_t o = ob + (size_t)w * 128;
        __nv_bfloat16 hi = __float2bfloat16(hst);
        ohi[o] = hi; olo[o] = __float2bfloat16(hst - __bfloat162float(hi));
    }
}

__global__ __launch_bounds__(256)
void scan_all(const float* __restrict__ in, __nv_bfloat16* __restrict__ ohi,
              __nv_bfloat16* __restrict__ olo, const float* __restrict__ ws,
              const float* __restrict__ bs)
{
    const int d = blockIdx.y;
    const int c = threadIdx.x & 31;
    const float wc = ws[d * 32 + c], bc = bs[d * 32 + c];
    if      (d == 0) scan_h_body<true >(in, ohi, olo, wc, bc, c, 0);    // up
    else if (d == 1) scan_w_body<false>(in, ohi, olo, wc, bc, c, 32);   // right
    else if (d == 2) scan_h_body<false>(in, ohi, olo, wc, bc, c, 64);   // down
    else             scan_w_body<true >(in, ohi, olo, wc, bc, c, 96);   // left
}

// ---------------------------------------------------------------------------
extern "C" void kernel_launch(void* const* d_in, const int* in_sizes, int n_in,
                              void* d_out, int out_size)
{
    const float* x   = (const float*)d_in[0];
    const float* w1  = (const float*)d_in[1];
    const float* w2  = (const float*)d_in[2];
    const float* w3  = (const float*)d_in[3];
    const float* wo  = (const float*)d_in[4];
    const float* i1w = (const float*)d_in[5];
    const float* i1b = (const float*)d_in[6];
    const float* i2w = (const float*)d_in[7];
    const float* i2b = (const float*)d_in[8];
    float* outp = (float*)d_out;

    float* gf;  __nv_bfloat16 *ghi, *glo;  char* gwb;
    cudaGetSymbolAddress((void**)&gf,  g_f32);
    cudaGetSymbolAddress((void**)&ghi, g_hi);
    cudaGetSymbolAddress((void**)&glo, g_lo);
    cudaGetSymbolAddress((void**)&gwb, g_wb);

    // smem: conv1 = 2*18944 + 2*10400 = 58688 ; conv2/3 = 2*74240 + 2*35360 = 219200
    cudaFuncSetAttribute(conv_mma<32,  false>, cudaFuncAttributeMaxDynamicSharedMemorySize, 58688);
    cudaFuncSetAttribute(conv_mma<128, false>, cudaFuncAttributeMaxDynamicSharedMemorySize, 219200);
    cudaFuncSetAttribute(conv_mma<128, true >, cudaFuncAttributeMaxDynamicSharedMemorySize, 219200);

    // prep B weight images (hi + lo)
    prep_w<<<(32 * 296  + 255) / 256, 256>>>(w1, gwb + 0,      gwb + 18944,  32);
    prep_w<<<(32 * 1160 + 255) / 256, 256>>>(w2, gwb + 37888,  gwb + 112128, 128);
    prep_w<<<(32 * 1160 + 255) / 256, 256>>>(w3, gwb + 186368, gwb + 260608, 128);

    // x -> NHWC bf16 split (32 ch)
    transpose_x<<<dim3(2048, 8), 256>>>(x, ghi, glo);

    dim3 cg(2, 64, 8);   // 4 output rows per CTA
    conv_mma<32, false><<<cg, 512, 58688>>>(ghi, glo, gwb + 0, nullptr, gf);

    scan_all<<<dim3(256, 4), 256>>>(gf, ghi, glo, i1w, i1b);

    conv_mma<128, false><<<cg, 512, 219200>>>(ghi, glo, gwb + 37888, nullptr, gf);

    scan_all<<<dim3(256, 4), 256>>>(gf, ghi, glo, i2w, i2b);

    conv_mma<128, true><<<cg, 512, 219200>>>(ghi, glo, gwb + 186368, wo, outp);
}

// round 10
// speedup vs baseline: 1.7661x; 1.7661x over previous
#include <cuda_runtime.h>
#include <cuda_fp16.h>
#include <math.h>
#include <stdint.h>

#define HW 65536

// ---------------------------------------------------------------------------
// Scratch (no allocations allowed)
// ---------------------------------------------------------------------------
__device__ float  g_f32[8ULL * 65536 * 32];    //  64 MB NHWC fp32 conv outputs
__device__ __half g_x16[8ULL * 65536 * 32];    //  32 MB NHWC fp16 x (conv1 input)
__device__ __half g_a16[8ULL * 65536 * 128];   // 128 MB NHWC fp16 irnn outputs
__device__ __align__(16) char g_wb[334848];    // prepped B fp16 (padded row-major, hi|lo)
// conv1: hi@0      lo@18944   (BSTR=592,  32 rows)
// conv2: hi@37888  lo@112128  (BSTR=2320, 32 rows)
// conv3: hi@186368 lo@260608

// ---------------------------------------------------------------------------
__device__ __forceinline__ uint32_t smem_u32(const void* p) {
    uint32_t a;
    asm("{ .reg .u64 t; cvta.to.shared.u64 t, %1; cvt.u32.u64 %0, t; }" : "=r"(a) : "l"(p));
    return a;
}
__device__ __forceinline__ void ldm4(uint32_t* r, uint32_t a) {
    asm volatile("ldmatrix.sync.aligned.m8n8.x4.shared.b16 {%0,%1,%2,%3}, [%4];"
                 : "=r"(r[0]), "=r"(r[1]), "=r"(r[2]), "=r"(r[3]) : "r"(a));
}
__device__ __forceinline__ void mma16816(float* c, const uint32_t* a, uint32_t b0, uint32_t b1) {
    asm volatile("mma.sync.aligned.m16n8k16.row.col.f32.f16.f16.f32 "
        "{%0,%1,%2,%3}, {%4,%5,%6,%7}, {%8,%9}, {%0,%1,%2,%3};"
        : "+f"(c[0]), "+f"(c[1]), "+f"(c[2]), "+f"(c[3])
        : "r"(a[0]), "r"(a[1]), "r"(a[2]), "r"(a[3]), "r"(b0), "r"(b1));
}
__device__ __forceinline__ void cp16(uint32_t saddr, const void* gaddr, int sz) {
    asm volatile("cp.async.cg.shared.global [%0], [%1], 16, %2;"
                 :: "r"(saddr), "l"(gaddr), "r"(sz));
}
__device__ __forceinline__ void cp_commit() { asm volatile("cp.async.commit_group;"); }
__device__ __forceinline__ void cp_wait0()  { asm volatile("cp.async.wait_group 0;"); }
__device__ __forceinline__ void cp_wait1()  { asm volatile("cp.async.wait_group 1;"); }

// ---------------------------------------------------------------------------
// Weight prep: fp32 [32][CIN][3][3] -> fp16 hi/lo padded row-major B images.
// ---------------------------------------------------------------------------
__global__ void prep_w(const float* __restrict__ w, char* __restrict__ bhi,
                       char* __restrict__ blo, int CIN)
{
    int K = 9 * CIN, KP = K + 8, BSTR = K * 2 + 16;
    int idx = blockIdx.x * 256 + threadIdx.x;
    if (idx >= 32 * KP) return;
    int n = idx / KP, k = idx - n * KP;
    float v = 0.f;
    if (k < K) {
        int dyi = k / (3 * CIN);
        int r   = k - dyi * 3 * CIN;
        int dxi = r / CIN;
        int c   = r - dxi * CIN;
        v = w[(n * CIN + c) * 9 + dyi * 3 + dxi];
    }
    __half hi = __float2half(v);
    __half lo = __float2half(v - __half2float(hi));
    int o = n * BSTR + k * 2;
    *(__half*)(bhi + o) = hi;
    *(__half*)(blo + o) = lo;
}

// ---------------------------------------------------------------------------
// x (NCHW fp32) -> NHWC fp16 (32 ch)
// ---------------------------------------------------------------------------
__global__ __launch_bounds__(256)
void transpose_x(const float* __restrict__ x, __half* __restrict__ o16)
{
    __shared__ float t[32][33];
    int b = blockIdx.y;
    int p0 = blockIdx.x * 32;
    int lane = threadIdx.x & 31, grp = threadIdx.x >> 5;
#pragma unroll
    for (int i = 0; i < 4; i++) {
        int c = grp + i * 8;
        t[c][lane] = x[((size_t)b * 32 + c) * HW + p0 + lane];
    }
    __syncthreads();
#pragma unroll
    for (int i = 0; i < 4; i++) {
        int p = grp + i * 8;
        o16[((size_t)b * HW + p0 + p) * 32 + lane] = __float2half(t[lane][p]);
    }
}

// ---------------------------------------------------------------------------
// HMMA implicit-GEMM 3x3 conv, 4 output rows/CTA, 8 warps, double-buffered A.
// A single fp16; B split-2 fp16 (hi+lo in smem).  acc += A*Bh + A*Bl.
// smem: [Bhi BBYT][Blo BBYT][A buf0 ABYT][A buf1 ABYT]
// ---------------------------------------------------------------------------
template<int CIN, bool FUSE>
__global__ __launch_bounds__(256, 1)
void conv_mma(const __half* __restrict__ a16, const char* __restrict__ wb,
              const float* __restrict__ wout, float* __restrict__ out)
{
    constexpr int K     = 9 * CIN;
    constexpr int ASTR  = CIN * 2 + 16;        // A row stride (bytes)
    constexpr int BSTR  = K * 2 + 16;          // B row stride (bytes)
    constexpr int BBYT  = 32 * BSTR;           // one split's B image
    constexpr int V4    = CIN / 8;             // uint4 per pixel-row
    constexpr int ABYT  = 130 * ASTR;          // one staged input row

    extern __shared__ __align__(16) char smem[];
    const int tid  = threadIdx.x;
    const int lane = tid & 31;
    const int wid  = tid >> 5;
    const int w0   = blockIdx.x << 7;
    const int h0   = blockIdx.y << 2;          // first of 4 output rows
    const int b    = blockIdx.z;

    const uint32_t s0   = smem_u32(smem);
    const uint32_t sBhi = s0;
    const uint32_t sBlo = s0 + BBYT;
    const uint32_t sA0  = s0 + 2 * BBYT;

    // group 0: B copy (hi|lo contiguous)
    {
        const int n4 = 2 * BBYT / 16;
        for (int i = tid; i < n4; i += 256)
            cp16(s0 + i * 16, wb + i * 16, 16);
        cp_commit();
    }

    // prefetch A input row for stage s into buffer s&1 (always commits a group)
    auto prefetch = [&](int s) {
        const int ir = h0 - 1 + s;
        const uint32_t abase = sA0 + (uint32_t)(s & 1) * ABYT;
        if ((unsigned)ir < 256u) {
            const size_t rowbase = ((size_t)b * HW + (size_t)ir * 256);
            for (int i = tid; i < 130 * V4; i += 256) {
                int px = i / V4, v = i - px * V4;
                int w  = w0 - 1 + px;
                int ok = ((unsigned)w < 256u);
                int wc = ok ? w : 0;
                cp16(abase + (uint32_t)(px * ASTR + v * 16),
                     (const char*)(a16 + (rowbase + wc) * CIN) + v * 16, ok ? 16 : 0);
            }
        }
        cp_commit();
    };
    prefetch(0);

    const int m0 = wid * 16;
    const uint32_t aRowOff = (uint32_t)(lane & 15) * ASTR + ((lane & 16) ? 16u : 0u);
    const uint32_t bLM = (uint32_t)((lane & 7) + ((lane & 16) ? 8 : 0)) * BSTR
                       + (uint32_t)((lane >> 3) & 1) * 16;

    float acc[4][16];
#pragma unroll
    for (int r = 0; r < 4; r++)
#pragma unroll
        for (int i = 0; i < 16; i++) acc[r][i] = 0.f;

    for (int s = 0; s < 6; s++) {
        const int ir = h0 - 1 + s;
        __syncthreads();                        // done reading buffer (s+1)&1
        if (s < 5) prefetch(s + 1);
        if (s < 5) cp_wait1(); else cp_wait0(); // prefetch(s) (and B) complete
        __syncthreads();
        if ((unsigned)ir >= 256u) continue;

        const uint32_t sA = sA0 + (uint32_t)(s & 1) * ABYT;

#pragma unroll
        for (int dx = 0; dx < 3; dx++) {
#pragma unroll
            for (int kc = 0; kc < CIN / 16; kc++) {
                uint32_t a[4];
                ldm4(a, sA + (uint32_t)(m0 + dx) * ASTR + kc * 32 + aRowOff);
#pragma unroll
                for (int r = 0; r < 4; r++) {
                    const int dy = s - r;
                    if (dy < 0 || dy > 2) continue;
                    const uint32_t kb = (uint32_t)(dy * 3 * CIN + dx * CIN + kc * 16) * 2;
                    uint32_t bh[4], bh2[4], bl[4], bl2[4];
                    ldm4(bh,  sBhi + bLM + kb);
                    ldm4(bh2, sBhi + bLM + kb + 16 * BSTR);
                    ldm4(bl,  sBlo + bLM + kb);
                    ldm4(bl2, sBlo + bLM + kb + 16 * BSTR);
                    float* a0 = acc[r];
                    mma16816(a0 + 0,  a, bh[0],  bh[1]);
                    mma16816(a0 + 4,  a, bh[2],  bh[3]);
                    mma16816(a0 + 8,  a, bh2[0], bh2[1]);
                    mma16816(a0 + 12, a, bh2[2], bh2[3]);
                    mma16816(a0 + 0,  a, bl[0],  bl[1]);
                    mma16816(a0 + 4,  a, bl[2],  bl[3]);
                    mma16816(a0 + 8,  a, bl2[0], bl2[1]);
                    mma16816(a0 + 12, a, bl2[2], bl2[3]);
                }
            }
        }
    }

    // epilogue (4 rows)
    const int prow = m0 + (lane >> 2);
#pragma unroll
    for (int r = 0; r < 4; r++) {
        const int h = h0 + r;
        if (!FUSE) {
            float* ob = out + ((size_t)b * HW + (size_t)h * 256 + w0) * 32;
#pragma unroll
            for (int nt = 0; nt < 4; nt++) {
                int ch = nt * 8 + (lane & 3) * 2;
                *(float2*)(ob + (size_t)prow * 32 + ch)       = make_float2(acc[r][nt * 4 + 0], acc[r][nt * 4 + 1]);
                *(float2*)(ob + (size_t)(prow + 8) * 32 + ch) = make_float2(acc[r][nt * 4 + 2], acc[r][nt * 4 + 3]);
            }
        } else {
            float s0v = 0.f, s1v = 0.f;
#pragma unroll
            for (int nt = 0; nt < 4; nt++) {
                int ch = nt * 8 + (lane & 3) * 2;
                float wa = __ldg(&wout[ch]), wb2 = __ldg(&wout[ch + 1]);
                s0v += fmaxf(acc[r][nt * 4 + 0], 0.f) * wa + fmaxf(acc[r][nt * 4 + 1], 0.f) * wb2;
                s1v += fmaxf(acc[r][nt * 4 + 2], 0.f) * wa + fmaxf(acc[r][nt * 4 + 3], 0.f) * wb2;
            }
            s0v += __shfl_xor_sync(0xffffffffu, s0v, 1);
            s0v += __shfl_xor_sync(0xffffffffu, s0v, 2);
            s1v += __shfl_xor_sync(0xffffffffu, s1v, 1);
            s1v += __shfl_xor_sync(0xffffffffu, s1v, 2);
            if ((lane & 3) == 0) {
                size_t ob = (size_t)b * HW + (size_t)h * 256 + w0;
                out[ob + prow]     = 1.0f / (1.0f + expf(-s0v));
                out[ob + prow + 8] = 1.0f / (1.0f + expf(-s1v));
            }
        }
    }
}

// ---------------------------------------------------------------------------
// IRNN: all 4 directional scans in ONE kernel (blockIdx.y = direction).
// Reads NHWC fp32 (32 ch); writes single fp16 into 128-ch NHWC at ch_off.
// ---------------------------------------------------------------------------
template<bool REV>
__device__ __forceinline__
void scan_h_body(const float* __restrict__ in, __half* __restrict__ o16,
                 float wc, float bc, int c, int ch_off)
{
    int t = blockIdx.x * 256 + threadIdx.x;      // over B*W*C = 65536
    int w = (t >> 5) & 255, b = t >> 13;
    const float* ip = in + (size_t)b * HW * 32 + (size_t)w * 32 + c;
    size_t ob = (size_t)b * HW * 128 + (size_t)w * 128 + ch_off + c;

    float hst = REV ? ip[(size_t)255 * 8192] : ip[0];
    o16[ob + (size_t)(REV ? 255 : 0) * 32768] = __float2half(hst);
#pragma unroll 8
    for (int i = 1; i < 256; i++) {
        int y = REV ? (255 - i) : i;
        hst = fmaxf(wc * hst + bc + ip[(size_t)y * 8192], 0.f);
        o16[ob + (size_t)y * 32768] = __float2half(hst);
    }
}

template<bool REV>
__device__ __forceinline__
void scan_w_body(const float* __restrict__ in, __half* __restrict__ o16,
                 float wc, float bc, int c, int ch_off)
{
    int t = blockIdx.x * 256 + threadIdx.x;      // over B*H*C = 65536
    int h = (t >> 5) & 255, b = t >> 13;
    const float* ip = in + (size_t)b * HW * 32 + (size_t)h * 8192 + c;
    size_t ob = (size_t)b * HW * 128 + (size_t)h * 32768 + ch_off + c;

    float hst = REV ? ip[255 * 32] : ip[0];
    o16[ob + (size_t)(REV ? 255 : 0) * 128] = __float2half(hst);
#pragma unroll 8
    for (int i = 1; i < 256; i++) {
        int w = REV ? (255 - i) : i;
        hst = fmaxf(wc * hst + bc + ip[w * 32], 0.f);
        o16[ob + (size_t)w * 128] = __float2half(hst);
    }
}

__global__ __launch_bounds__(256)
void scan_all(const float* __restrict__ in, __half* __restrict__ o16,
              const float* __restrict__ ws, const float* __restrict__ bs)
{
    const int d = blockIdx.y;
    const int c = threadIdx.x & 31;
    const float wc = ws[d * 32 + c], bc = bs[d * 32 + c];
    if      (d == 0) scan_h_body<true >(in, o16, wc, bc, c, 0);    // up
    else if (d == 1) scan_w_body<false>(in, o16, wc, bc, c, 32);   // right
    else if (d == 2) scan_h_body<false>(in, o16, wc, bc, c, 64);   // down
    else             scan_w_body<true >(in, o16, wc, bc, c, 96);   // left
}

// ---------------------------------------------------------------------------
extern "C" void kernel_launch(void* const* d_in, const int* in_sizes, int n_in,
                              void* d_out, int out_size)
{
    const float* x   = (const float*)d_in[0];
    const float* w1  = (const float*)d_in[1];
    const float* w2  = (const float*)d_in[2];
    const float* w3  = (const float*)d_in[3];
    const float* wo  = (const float*)d_in[4];
    const float* i1w = (const float*)d_in[5];
    const float* i1b = (const float*)d_in[6];
    const float* i2w = (const float*)d_in[7];
    const float* i2b = (const float*)d_in[8];
    float* outp = (float*)d_out;

    float* gf;  __half *gx, *ga;  char* gwb;
    cudaGetSymbolAddress((void**)&gf,  g_f32);
    cudaGetSymbolAddress((void**)&gx,  g_x16);
    cudaGetSymbolAddress((void**)&ga,  g_a16);
    cudaGetSymbolAddress((void**)&gwb, g_wb);

    // smem: conv1 = 2*18944 + 2*10400 = 58688 ; conv2/3 = 2*74240 + 2*35360 = 219200
    cudaFuncSetAttribute(conv_mma<32,  false>, cudaFuncAttributeMaxDynamicSharedMemorySize, 58688);
    cudaFuncSetAttribute(conv_mma<128, false>, cudaFuncAttributeMaxDynamicSharedMemorySize, 219200);
    cudaFuncSetAttribute(conv_mma<128, true >, cudaFuncAttributeMaxDynamicSharedMemorySize, 219200);

    // prep B weight images (fp16 hi + lo)
    prep_w<<<(32 * 296  + 255) / 256, 256>>>(w1, gwb + 0,      gwb + 18944,  32);
    prep_w<<<(32 * 1160 + 255) / 256, 256>>>(w2, gwb + 37888,  gwb + 112128, 128);
    prep_w<<<(32 * 1160 + 255) / 256, 256>>>(w3, gwb + 186368, gwb + 260608, 128);

    // x -> NHWC fp16 (32 ch)
    transpose_x<<<dim3(2048, 8), 256>>>(x, gx);

    dim3 cg(2, 64, 8);   // 4 output rows per CTA
    conv_mma<32, false><<<cg, 256, 58688>>>(gx, gwb + 0, nullptr, gf);

    scan_all<<<dim3(256, 4), 256>>>(gf, ga, i1w, i1b);

    conv_mma<128, false><<<cg, 256, 219200>>>(ga, gwb + 37888, nullptr, gf);

    scan_all<<<dim3(256, 4), 256>>>(gf, ga, i2w, i2b);

    conv_mma<128, true><<<cg, 256, 219200>>>(ga, gwb + 186368, wo, outp);
}

// round 11
// speedup vs baseline: 2.2515x; 1.2748x over previous
#include <cuda_runtime.h>
#include <cuda_fp16.h>
#include <math.h>
#include <stdint.h>

#define HW 65536

// ---------------------------------------------------------------------------
// Scratch (no allocations allowed)
// ---------------------------------------------------------------------------
__device__ float  g_f32[8ULL * 65536 * 32];    //  64 MB NHWC fp32 conv outputs
__device__ __half g_x16[8ULL * 65536 * 32];    //  32 MB NHWC fp16 x (conv1 input)
__device__ __half g_a16[8ULL * 65536 * 128];   // 128 MB NHWC fp16 irnn outputs
__device__ __align__(16) char g_wb[167424];    // prepped B fp16 (padded row-major)
// conv1: @0 (18944, BSTR=592) ; conv2: @18944 (74240, BSTR=2320) ; conv3: @93184

// ---------------------------------------------------------------------------
__device__ __forceinline__ uint32_t smem_u32(const void* p) {
    uint32_t a;
    asm("{ .reg .u64 t; cvta.to.shared.u64 t, %1; cvt.u32.u64 %0, t; }" : "=r"(a) : "l"(p));
    return a;
}
__device__ __forceinline__ void ldm4(uint32_t* r, uint32_t a) {
    asm volatile("ldmatrix.sync.aligned.m8n8.x4.shared.b16 {%0,%1,%2,%3}, [%4];"
                 : "=r"(r[0]), "=r"(r[1]), "=r"(r[2]), "=r"(r[3]) : "r"(a));
}
__device__ __forceinline__ void mma16816(float* c, const uint32_t* a, uint32_t b0, uint32_t b1) {
    asm volatile("mma.sync.aligned.m16n8k16.row.col.f32.f16.f16.f32 "
        "{%0,%1,%2,%3}, {%4,%5,%6,%7}, {%8,%9}, {%0,%1,%2,%3};"
        : "+f"(c[0]), "+f"(c[1]), "+f"(c[2]), "+f"(c[3])
        : "r"(a[0]), "r"(a[1]), "r"(a[2]), "r"(a[3]), "r"(b0), "r"(b1));
}
__device__ __forceinline__ void cp16(uint32_t saddr, const void* gaddr, int sz) {
    asm volatile("cp.async.cg.shared.global [%0], [%1], 16, %2;"
                 :: "r"(saddr), "l"(gaddr), "r"(sz));
}
__device__ __forceinline__ void cp_commit() { asm volatile("cp.async.commit_group;"); }
__device__ __forceinline__ void cp_wait0()  { asm volatile("cp.async.wait_group 0;"); }
__device__ __forceinline__ void cp_wait1()  { asm volatile("cp.async.wait_group 1;"); }

// ---------------------------------------------------------------------------
// Weight prep: fp32 [32][CIN][3][3] -> fp16 padded row-major B image.
// ---------------------------------------------------------------------------
__global__ void prep_w(const float* __restrict__ w, char* __restrict__ bimg, int CIN)
{
    int K = 9 * CIN, KP = K + 8, BSTR = K * 2 + 16;
    int idx = blockIdx.x * 256 + threadIdx.x;
    if (idx >= 32 * KP) return;
    int n = idx / KP, k = idx - n * KP;
    float v = 0.f;
    if (k < K) {
        int dyi = k / (3 * CIN);
        int r   = k - dyi * 3 * CIN;
        int dxi = r / CIN;
        int c   = r - dxi * CIN;
        v = w[(n * CIN + c) * 9 + dyi * 3 + dxi];
    }
    *(__half*)(bimg + n * BSTR + k * 2) = __float2half(v);
}

// ---------------------------------------------------------------------------
// x (NCHW fp32) -> NHWC fp16 (32 ch)
// ---------------------------------------------------------------------------
__global__ __launch_bounds__(256)
void transpose_x(const float* __restrict__ x, __half* __restrict__ o16)
{
    __shared__ float t[32][33];
    int b = blockIdx.y;
    int p0 = blockIdx.x * 32;
    int lane = threadIdx.x & 31, grp = threadIdx.x >> 5;
#pragma unroll
    for (int i = 0; i < 4; i++) {
        int c = grp + i * 8;
        t[c][lane] = x[((size_t)b * 32 + c) * HW + p0 + lane];
    }
    __syncthreads();
#pragma unroll
    for (int i = 0; i < 4; i++) {
        int p = grp + i * 8;
        o16[((size_t)b * HW + p0 + p) * 32 + lane] = __float2half(t[lane][p]);
    }
}

// ---------------------------------------------------------------------------
// HMMA implicit-GEMM 3x3 conv, 4 output rows/CTA, 8 warps, double-buffered A.
// A fp16; B fp16 (single).  acc += A*B.
// smem: [B BBYT][A buf0 ABYT][A buf1 ABYT]
// ---------------------------------------------------------------------------
template<int CIN, bool FUSE>
__global__ __launch_bounds__(256, 1)
void conv_mma(const __half* __restrict__ a16, const char* __restrict__ wb,
              const float* __restrict__ wout, float* __restrict__ out)
{
    constexpr int K     = 9 * CIN;
    constexpr int ASTR  = CIN * 2 + 16;        // A row stride (bytes)
    constexpr int BSTR  = K * 2 + 16;          // B row stride (bytes)
    constexpr int BBYT  = 32 * BSTR;           // B image
    constexpr int V4    = CIN / 8;             // uint4 per pixel-row
    constexpr int ABYT  = 130 * ASTR;          // one staged input row

    extern __shared__ __align__(16) char smem[];
    const int tid  = threadIdx.x;
    const int lane = tid & 31;
    const int wid  = tid >> 5;
    const int w0   = blockIdx.x << 7;
    const int h0   = blockIdx.y << 2;          // first of 4 output rows
    const int b    = blockIdx.z;

    const uint32_t s0  = smem_u32(smem);
    const uint32_t sB  = s0;
    const uint32_t sA0 = s0 + BBYT;

    // group 0: B copy
    {
        const int n4 = BBYT / 16;
        for (int i = tid; i < n4; i += 256)
            cp16(sB + i * 16, wb + i * 16, 16);
        cp_commit();
    }

    // prefetch A input row for stage s into buffer s&1 (always commits a group)
    auto prefetch = [&](int s) {
        const int ir = h0 - 1 + s;
        const uint32_t abase = sA0 + (uint32_t)(s & 1) * ABYT;
        if ((unsigned)ir < 256u) {
            const size_t rowbase = ((size_t)b * HW + (size_t)ir * 256);
            for (int i = tid; i < 130 * V4; i += 256) {
                int px = i / V4, v = i - px * V4;
                int w  = w0 - 1 + px;
                int ok = ((unsigned)w < 256u);
                int wc = ok ? w : 0;
                cp16(abase + (uint32_t)(px * ASTR + v * 16),
                     (const char*)(a16 + (rowbase + wc) * CIN) + v * 16, ok ? 16 : 0);
            }
        }
        cp_commit();
    };
    prefetch(0);

    const int m0 = wid * 16;
    const uint32_t aRowOff = (uint32_t)(lane & 15) * ASTR + ((lane & 16) ? 16u : 0u);
    const uint32_t bLM = (uint32_t)((lane & 7) + ((lane & 16) ? 8 : 0)) * BSTR
                       + (uint32_t)((lane >> 3) & 1) * 16;

    float acc[4][16];
#pragma unroll
    for (int r = 0; r < 4; r++)
#pragma unroll
        for (int i = 0; i < 16; i++) acc[r][i] = 0.f;

    for (int s = 0; s < 6; s++) {
        const int ir = h0 - 1 + s;
        __syncthreads();                        // done reading buffer (s+1)&1
        if (s < 5) prefetch(s + 1);
        if (s < 5) cp_wait1(); else cp_wait0(); // prefetch(s) (and B) complete
        __syncthreads();
        if ((unsigned)ir >= 256u) continue;

        const uint32_t sA = sA0 + (uint32_t)(s & 1) * ABYT;

#pragma unroll
        for (int dx = 0; dx < 3; dx++) {
#pragma unroll
            for (int kc = 0; kc < CIN / 16; kc++) {
                uint32_t a[4];
                ldm4(a, sA + (uint32_t)(m0 + dx) * ASTR + kc * 32 + aRowOff);
#pragma unroll
                for (int r = 0; r < 4; r++) {
                    const int dy = s - r;
                    if (dy < 0 || dy > 2) continue;
                    const uint32_t kb = (uint32_t)(dy * 3 * CIN + dx * CIN + kc * 16) * 2;
                    uint32_t bh[4], bh2[4];
                    ldm4(bh,  sB + bLM + kb);
                    ldm4(bh2, sB + bLM + kb + 16 * BSTR);
                    float* a0 = acc[r];
                    mma16816(a0 + 0,  a, bh[0],  bh[1]);
                    mma16816(a0 + 4,  a, bh[2],  bh[3]);
                    mma16816(a0 + 8,  a, bh2[0], bh2[1]);
                    mma16816(a0 + 12, a, bh2[2], bh2[3]);
                }
            }
        }
    }

    // epilogue (4 rows)
    const int prow = m0 + (lane >> 2);
#pragma unroll
    for (int r = 0; r < 4; r++) {
        const int h = h0 + r;
        if (!FUSE) {
            float* ob = out + ((size_t)b * HW + (size_t)h * 256 + w0) * 32;
#pragma unroll
            for (int nt = 0; nt < 4; nt++) {
                int ch = nt * 8 + (lane & 3) * 2;
                *(float2*)(ob + (size_t)prow * 32 + ch)       = make_float2(acc[r][nt * 4 + 0], acc[r][nt * 4 + 1]);
                *(float2*)(ob + (size_t)(prow + 8) * 32 + ch) = make_float2(acc[r][nt * 4 + 2], acc[r][nt * 4 + 3]);
            }
        } else {
            float s0v = 0.f, s1v = 0.f;
#pragma unroll
            for (int nt = 0; nt < 4; nt++) {
                int ch = nt * 8 + (lane & 3) * 2;
                float wa = __ldg(&wout[ch]), wb2 = __ldg(&wout[ch + 1]);
                s0v += fmaxf(acc[r][nt * 4 + 0], 0.f) * wa + fmaxf(acc[r][nt * 4 + 1], 0.f) * wb2;
                s1v += fmaxf(acc[r][nt * 4 + 2], 0.f) * wa + fmaxf(acc[r][nt * 4 + 3], 0.f) * wb2;
            }
            s0v += __shfl_xor_sync(0xffffffffu, s0v, 1);
            s0v += __shfl_xor_sync(0xffffffffu, s0v, 2);
            s1v += __shfl_xor_sync(0xffffffffu, s1v, 1);
            s1v += __shfl_xor_sync(0xffffffffu, s1v, 2);
            if ((lane & 3) == 0) {
                size_t ob = (size_t)b * HW + (size_t)h * 256 + w0;
                out[ob + prow]     = 1.0f / (1.0f + expf(-s0v));
                out[ob + prow + 8] = 1.0f / (1.0f + expf(-s1v));
            }
        }
    }
}

// ---------------------------------------------------------------------------
// IRNN: all 4 directional scans in ONE kernel (blockIdx.y = direction).
// Reads NHWC fp32 (32 ch); writes single fp16 into 128-ch NHWC at ch_off.
// ---------------------------------------------------------------------------
template<bool REV>
__device__ __forceinline__
void scan_h_body(const float* __restrict__ in, __half* __restrict__ o16,
                 float wc, float bc, int c, int ch_off)
{
    int t = blockIdx.x * 256 + threadIdx.x;      // over B*W*C = 65536
    int w = (t >> 5) & 255, b = t >> 13;
    const float* ip = in + (size_t)b * HW * 32 + (size_t)w * 32 + c;
    size_t ob = (size_t)b * HW * 128 + (size_t)w * 128 + ch_off + c;

    float hst = REV ? ip[(size_t)255 * 8192] : ip[0];
    o16[ob + (size_t)(REV ? 255 : 0) * 32768] = __float2half(hst);
#pragma unroll 8
    for (int i = 1; i < 256; i++) {
        int y = REV ? (255 - i) : i;
        hst = fmaxf(wc * hst + bc + ip[(size_t)y * 8192], 0.f);
        o16[ob + (size_t)y * 32768] = __float2half(hst);
    }
}

template<bool REV>
__device__ __forceinline__
void scan_w_body(const float* __restrict__ in, __half* __restrict__ o16,
                 float wc, float bc, int c, int ch_off)
{
    int t = blockIdx.x * 256 + threadIdx.x;      // over B*H*C = 65536
    int h = (t >> 5) & 255, b = t >> 13;
    const float* ip = in + (size_t)b * HW * 32 + (size_t)h * 8192 + c;
    size_t ob = (size_t)b * HW * 128 + (size_t)h * 32768 + ch_off + c;

    float hst = REV ? ip[255 * 32] : ip[0];
    o16[ob + (size_t)(REV ? 255 : 0) * 128] = __float2half(hst);
#pragma unroll 8
    for (int i = 1; i < 256; i++) {
        int w = REV ? (255 - i) : i;
        hst = fmaxf(wc * hst + bc + ip[w * 32], 0.f);
        o16[ob + (size_t)w * 128] = __float2half(hst);
    }
}

__global__ __launch_bounds__(256)
void scan_all(const float* __restrict__ in, __half* __restrict__ o16,
              const float* __restrict__ ws, const float* __restrict__ bs)
{
    const int d = blockIdx.y;
    const int c = threadIdx.x & 31;
    const float wc = ws[d * 32 + c], bc = bs[d * 32 + c];
    if      (d == 0) scan_h_body<true >(in, o16, wc, bc, c, 0);    // up
    else if (d == 1) scan_w_body<false>(in, o16, wc, bc, c, 32);   // right
    else if (d == 2) scan_h_body<false>(in, o16, wc, bc, c, 64);   // down
    else             scan_w_body<true >(in, o16, wc, bc, c, 96);   // left
}

// ---------------------------------------------------------------------------
extern "C" void kernel_launch(void* const* d_in, const int* in_sizes, int n_in,
                              void* d_out, int out_size)
{
    const float* x   = (const float*)d_in[0];
    const float* w1  = (const float*)d_in[1];
    const float* w2  = (const float*)d_in[2];
    const float* w3  = (const float*)d_in[3];
    const float* wo  = (const float*)d_in[4];
    const float* i1w = (const float*)d_in[5];
    const float* i1b = (const float*)d_in[6];
    const float* i2w = (const float*)d_in[7];
    const float* i2b = (const float*)d_in[8];
    float* outp = (float*)d_out;

    float* gf;  __half *gx, *ga;  char* gwb;
    cudaGetSymbolAddress((void**)&gf,  g_f32);
    cudaGetSymbolAddress((void**)&gx,  g_x16);
    cudaGetSymbolAddress((void**)&ga,  g_a16);
    cudaGetSymbolAddress((void**)&gwb, g_wb);

    // smem: conv1 = 18944 + 2*10400 = 39744 ; conv2/3 = 74240 + 2*35360 = 144960
    cudaFuncSetAttribute(conv_mma<32,  false>, cudaFuncAttributeMaxDynamicSharedMemorySize, 39744);
    cudaFuncSetAttribute(conv_mma<128, false>, cudaFuncAttributeMaxDynamicSharedMemorySize, 144960);
    cudaFuncSetAttribute(conv_mma<128, true >, cudaFuncAttributeMaxDynamicSharedMemorySize, 144960);

    // prep B weight images (fp16)
    prep_w<<<(32 * 296  + 255) / 256, 256>>>(w1, gwb + 0,     32);
    prep_w<<<(32 * 1160 + 255) / 256, 256>>>(w2, gwb + 18944, 128);
    prep_w<<<(32 * 1160 + 255) / 256, 256>>>(w3, gwb + 93184, 128);

    // x -> NHWC fp16 (32 ch)
    transpose_x<<<dim3(2048, 8), 256>>>(x, gx);

    dim3 cg(2, 64, 8);   // 4 output rows per CTA
    conv_mma<32, false><<<cg, 256, 39744>>>(gx, gwb + 0, nullptr, gf);

    scan_all<<<dim3(256, 4), 256>>>(gf, ga, i1w, i1b);

    conv_mma<128, false><<<cg, 256, 144960>>>(ga, gwb + 18944, nullptr, gf);

    scan_all<<<dim3(256, 4), 256>>>(gf, ga, i2w, i2b);

    conv_mma<128, true><<<cg, 256, 144960>>>(ga, gwb + 93184, wo, outp);
}

// round 12
// speedup vs baseline: 2.2823x; 1.0137x over previous
#include <cuda_runtime.h>
#include <cuda_fp16.h>
#include <math.h>
#include <stdint.h>

#define HW 65536

// ---------------------------------------------------------------------------
// Scratch (no allocations allowed)
// ---------------------------------------------------------------------------
__device__ __half g_c16[8ULL * 65536 * 32];    //  32 MB NHWC fp16 conv outputs
__device__ __half g_x16[8ULL * 65536 * 32];    //  32 MB NHWC fp16 x (conv1 input)
__device__ __half g_a16[8ULL * 65536 * 128];   // 128 MB NHWC fp16 irnn outputs
__device__ __align__(16) char g_wb[167424];    // prepped B fp16 (padded row-major)
// conv1: @0 (18944, BSTR=592) ; conv2: @18944 (74240, BSTR=2320) ; conv3: @93184

// ---------------------------------------------------------------------------
__device__ __forceinline__ uint32_t smem_u32(const void* p) {
    uint32_t a;
    asm("{ .reg .u64 t; cvta.to.shared.u64 t, %1; cvt.u32.u64 %0, t; }" : "=r"(a) : "l"(p));
    return a;
}
__device__ __forceinline__ void ldm4(uint32_t* r, uint32_t a) {
    asm volatile("ldmatrix.sync.aligned.m8n8.x4.shared.b16 {%0,%1,%2,%3}, [%4];"
                 : "=r"(r[0]), "=r"(r[1]), "=r"(r[2]), "=r"(r[3]) : "r"(a));
}
__device__ __forceinline__ void mma16816(float* c, const uint32_t* a, uint32_t b0, uint32_t b1) {
    asm volatile("mma.sync.aligned.m16n8k16.row.col.f32.f16.f16.f32 "
        "{%0,%1,%2,%3}, {%4,%5,%6,%7}, {%8,%9}, {%0,%1,%2,%3};"
        : "+f"(c[0]), "+f"(c[1]), "+f"(c[2]), "+f"(c[3])
        : "r"(a[0]), "r"(a[1]), "r"(a[2]), "r"(a[3]), "r"(b0), "r"(b1));
}
__device__ __forceinline__ void cp16(uint32_t saddr, const void* gaddr, int sz) {
    asm volatile("cp.async.cg.shared.global [%0], [%1], 16, %2;"
                 :: "r"(saddr), "l"(gaddr), "r"(sz));
}
__device__ __forceinline__ void cp_commit() { asm volatile("cp.async.commit_group;"); }
__device__ __forceinline__ void cp_wait0()  { asm volatile("cp.async.wait_group 0;"); }
__device__ __forceinline__ void cp_wait1()  { asm volatile("cp.async.wait_group 1;"); }

// ---------------------------------------------------------------------------
// Weight prep: fp32 [32][CIN][3][3] -> fp16 padded row-major B image.
// ---------------------------------------------------------------------------
__global__ void prep_w(const float* __restrict__ w, char* __restrict__ bimg, int CIN)
{
    int K = 9 * CIN, KP = K + 8, BSTR = K * 2 + 16;
    int idx = blockIdx.x * 256 + threadIdx.x;
    if (idx >= 32 * KP) return;
    int n = idx / KP, k = idx - n * KP;
    float v = 0.f;
    if (k < K) {
        int dyi = k / (3 * CIN);
        int r   = k - dyi * 3 * CIN;
        int dxi = r / CIN;
        int c   = r - dxi * CIN;
        v = w[(n * CIN + c) * 9 + dyi * 3 + dxi];
    }
    *(__half*)(bimg + n * BSTR + k * 2) = __float2half(v);
}

// ---------------------------------------------------------------------------
// x (NCHW fp32) -> NHWC fp16 (32 ch)
// ---------------------------------------------------------------------------
__global__ __launch_bounds__(256)
void transpose_x(const float* __restrict__ x, __half* __restrict__ o16)
{
    __shared__ float t[32][33];
    int b = blockIdx.y;
    int p0 = blockIdx.x * 32;
    int lane = threadIdx.x & 31, grp = threadIdx.x >> 5;
#pragma unroll
    for (int i = 0; i < 4; i++) {
        int c = grp + i * 8;
        t[c][lane] = x[((size_t)b * 32 + c) * HW + p0 + lane];
    }
    __syncthreads();
#pragma unroll
    for (int i = 0; i < 4; i++) {
        int p = grp + i * 8;
        o16[((size_t)b * HW + p0 + p) * 32 + lane] = __float2half(t[lane][p]);
    }
}

// ---------------------------------------------------------------------------
// HMMA implicit-GEMM 3x3 conv, 4 output rows/CTA, 8 warps, double-buffered A.
// A fp16; B fp16.  acc += A*B.  Non-FUSE output: fp16 NHWC.
// smem: [B BBYT][A buf0 ABYT][A buf1 ABYT]
// ---------------------------------------------------------------------------
template<int CIN, bool FUSE>
__global__ __launch_bounds__(256, 1)
void conv_mma(const __half* __restrict__ a16, const char* __restrict__ wb,
              const float* __restrict__ wout, void* __restrict__ outv)
{
    constexpr int K     = 9 * CIN;
    constexpr int ASTR  = CIN * 2 + 16;        // A row stride (bytes)
    constexpr int BSTR  = K * 2 + 16;          // B row stride (bytes)
    constexpr int BBYT  = 32 * BSTR;           // B image
    constexpr int V4    = CIN / 8;             // uint4 per pixel-row
    constexpr int ABYT  = 130 * ASTR;          // one staged input row

    extern __shared__ __align__(16) char smem[];
    const int tid  = threadIdx.x;
    const int lane = tid & 31;
    const int wid  = tid >> 5;
    const int w0   = blockIdx.x << 7;
    const int h0   = blockIdx.y << 2;          // first of 4 output rows
    const int b    = blockIdx.z;

    const uint32_t s0  = smem_u32(smem);
    const uint32_t sB  = s0;
    const uint32_t sA0 = s0 + BBYT;

    // group 0: B copy
    {
        const int n4 = BBYT / 16;
        for (int i = tid; i < n4; i += 256)
            cp16(sB + i * 16, wb + i * 16, 16);
        cp_commit();
    }

    // prefetch A input row for stage s into buffer s&1 (always commits a group)
    auto prefetch = [&](int s) {
        const int ir = h0 - 1 + s;
        const uint32_t abase = sA0 + (uint32_t)(s & 1) * ABYT;
        if ((unsigned)ir < 256u) {
            const size_t rowbase = ((size_t)b * HW + (size_t)ir * 256);
            for (int i = tid; i < 130 * V4; i += 256) {
                int px = i / V4, v = i - px * V4;
                int w  = w0 - 1 + px;
                int ok = ((unsigned)w < 256u);
                int wc = ok ? w : 0;
                cp16(abase + (uint32_t)(px * ASTR + v * 16),
                     (const char*)(a16 + (rowbase + wc) * CIN) + v * 16, ok ? 16 : 0);
            }
        }
        cp_commit();
    };
    prefetch(0);

    const int m0 = wid * 16;
    const uint32_t aRowOff = (uint32_t)(lane & 15) * ASTR + ((lane & 16) ? 16u : 0u);
    const uint32_t bLM = (uint32_t)((lane & 7) + ((lane & 16) ? 8 : 0)) * BSTR
                       + (uint32_t)((lane >> 3) & 1) * 16;

    float acc[4][16];
#pragma unroll
    for (int r = 0; r < 4; r++)
#pragma unroll
        for (int i = 0; i < 16; i++) acc[r][i] = 0.f;

    for (int s = 0; s < 6; s++) {
        const int ir = h0 - 1 + s;
        __syncthreads();                        // done reading buffer (s+1)&1
        if (s < 5) prefetch(s + 1);
        if (s < 5) cp_wait1(); else cp_wait0(); // prefetch(s) (and B) complete
        __syncthreads();
        if ((unsigned)ir >= 256u) continue;

        const uint32_t sA = sA0 + (uint32_t)(s & 1) * ABYT;

#pragma unroll
        for (int dx = 0; dx < 3; dx++) {
#pragma unroll
            for (int kc = 0; kc < CIN / 16; kc++) {
                uint32_t a[4];
                ldm4(a, sA + (uint32_t)(m0 + dx) * ASTR + kc * 32 + aRowOff);
#pragma unroll
                for (int r = 0; r < 4; r++) {
                    const int dy = s - r;
                    if (dy < 0 || dy > 2) continue;
                    const uint32_t kb = (uint32_t)(dy * 3 * CIN + dx * CIN + kc * 16) * 2;
                    uint32_t bh[4], bh2[4];
                    ldm4(bh,  sB + bLM + kb);
                    ldm4(bh2, sB + bLM + kb + 16 * BSTR);
                    float* a0 = acc[r];
                    mma16816(a0 + 0,  a, bh[0],  bh[1]);
                    mma16816(a0 + 4,  a, bh[2],  bh[3]);
                    mma16816(a0 + 8,  a, bh2[0], bh2[1]);
                    mma16816(a0 + 12, a, bh2[2], bh2[3]);
                }
            }
        }
    }

    // epilogue (4 rows)
    const int prow = m0 + (lane >> 2);
#pragma unroll
    for (int r = 0; r < 4; r++) {
        const int h = h0 + r;
        if (!FUSE) {
            __half* ob = (__half*)outv + ((size_t)b * HW + (size_t)h * 256 + w0) * 32;
#pragma unroll
            for (int nt = 0; nt < 4; nt++) {
                int ch = nt * 8 + (lane & 3) * 2;
                *(__half2*)(ob + (size_t)prow * 32 + ch) =
                    __floats2half2_rn(acc[r][nt * 4 + 0], acc[r][nt * 4 + 1]);
                *(__half2*)(ob + (size_t)(prow + 8) * 32 + ch) =
                    __floats2half2_rn(acc[r][nt * 4 + 2], acc[r][nt * 4 + 3]);
            }
        } else {
            float s0v = 0.f, s1v = 0.f;
#pragma unroll
            for (int nt = 0; nt < 4; nt++) {
                int ch = nt * 8 + (lane & 3) * 2;
                float wa = __ldg(&wout[ch]), wb2 = __ldg(&wout[ch + 1]);
                s0v += fmaxf(acc[r][nt * 4 + 0], 0.f) * wa + fmaxf(acc[r][nt * 4 + 1], 0.f) * wb2;
                s1v += fmaxf(acc[r][nt * 4 + 2], 0.f) * wa + fmaxf(acc[r][nt * 4 + 3], 0.f) * wb2;
            }
            s0v += __shfl_xor_sync(0xffffffffu, s0v, 1);
            s0v += __shfl_xor_sync(0xffffffffu, s0v, 2);
            s1v += __shfl_xor_sync(0xffffffffu, s1v, 1);
            s1v += __shfl_xor_sync(0xffffffffu, s1v, 2);
            if ((lane & 3) == 0) {
                float* outp = (float*)outv;
                size_t ob = (size_t)b * HW + (size_t)h * 256 + w0;
                outp[ob + prow]     = 1.0f / (1.0f + expf(-s0v));
                outp[ob + prow + 8] = 1.0f / (1.0f + expf(-s1v));
            }
        }
    }
}

// ---------------------------------------------------------------------------
// IRNN: all 4 directional scans in ONE kernel (blockIdx.y = direction).
// Reads NHWC fp16 (32 ch); writes fp16 into 128-ch NHWC at ch_off.
// ---------------------------------------------------------------------------
template<bool REV>
__device__ __forceinline__
void scan_h_body(const __half* __restrict__ in, __half* __restrict__ o16,
                 float wc, float bc, int c, int ch_off)
{
    int t = blockIdx.x * 256 + threadIdx.x;      // over B*W*C = 65536
    int w = (t >> 5) & 255, b = t >> 13;
    const __half* ip = in + (size_t)b * HW * 32 + (size_t)w * 32 + c;
    size_t ob = (size_t)b * HW * 128 + (size_t)w * 128 + ch_off + c;

    float hst = __half2float(REV ? ip[(size_t)255 * 8192] : ip[0]);
    o16[ob + (size_t)(REV ? 255 : 0) * 32768] = __float2half(hst);
#pragma unroll 8
    for (int i = 1; i < 256; i++) {
        int y = REV ? (255 - i) : i;
        hst = fmaxf(wc * hst + bc + __half2float(ip[(size_t)y * 8192]), 0.f);
        o16[ob + (size_t)y * 32768] = __float2half(hst);
    }
}

template<bool REV>
__device__ __forceinline__
void scan_w_body(const __half* __restrict__ in, __half* __restrict__ o16,
                 float wc, float bc, int c, int ch_off)
{
    int t = blockIdx.x * 256 + threadIdx.x;      // over B*H*C = 65536
    int h = (t >> 5) & 255, b = t >> 13;
    const __half* ip = in + (size_t)b * HW * 32 + (size_t)h * 8192 + c;
    size_t ob = (size_t)b * HW * 128 + (size_t)h * 32768 + ch_off + c;

    float hst = __half2float(REV ? ip[255 * 32] : ip[0]);
    o16[ob + (size_t)(REV ? 255 : 0) * 128] = __float2half(hst);
#pragma unroll 8
    for (int i = 1; i < 256; i++) {
        int w = REV ? (255 - i) : i;
        hst = fmaxf(wc * hst + bc + __half2float(ip[w * 32]), 0.f);
        o16[ob + (size_t)w * 128] = __float2half(hst);
    }
}

__global__ __launch_bounds__(256)
void scan_all(const __half* __restrict__ in, __half* __restrict__ o16,
              const float* __restrict__ ws, const float* __restrict__ bs)
{
    const int d = blockIdx.y;
    const int c = threadIdx.x & 31;
    const float wc = ws[d * 32 + c], bc = bs[d * 32 + c];
    if      (d == 0) scan_h_body<true >(in, o16, wc, bc, c, 0);    // up
    else if (d == 1) scan_w_body<false>(in, o16, wc, bc, c, 32);   // right
    else if (d == 2) scan_h_body<false>(in, o16, wc, bc, c, 64);   // down
    else             scan_w_body<true >(in, o16, wc, bc, c, 96);   // left
}

// ---------------------------------------------------------------------------
extern "C" void kernel_launch(void* const* d_in, const int* in_sizes, int n_in,
                              void* d_out, int out_size)
{
    const float* x   = (const float*)d_in[0];
    const float* w1  = (const float*)d_in[1];
    const float* w2  = (const float*)d_in[2];
    const float* w3  = (const float*)d_in[3];
    const float* wo  = (const float*)d_in[4];
    const float* i1w = (const float*)d_in[5];
    const float* i1b = (const float*)d_in[6];
    const float* i2w = (const float*)d_in[7];
    const float* i2b = (const float*)d_in[8];
    float* outp = (float*)d_out;

    __half *gc, *gx, *ga;  char* gwb;
    cudaGetSymbolAddress((void**)&gc,  g_c16);
    cudaGetSymbolAddress((void**)&gx,  g_x16);
    cudaGetSymbolAddress((void**)&ga,  g_a16);
    cudaGetSymbolAddress((void**)&gwb, g_wb);

    // smem: conv1 = 18944 + 2*10400 = 39744 ; conv2/3 = 74240 + 2*35360 = 144960
    cudaFuncSetAttribute(conv_mma<32,  false>, cudaFuncAttributeMaxDynamicSharedMemorySize, 39744);
    cudaFuncSetAttribute(conv_mma<128, false>, cudaFuncAttributeMaxDynamicSharedMemorySize, 144960);
    cudaFuncSetAttribute(conv_mma<128, true >, cudaFuncAttributeMaxDynamicSharedMemorySize, 144960);

    // prep B weight images (fp16)
    prep_w<<<(32 * 296  + 255) / 256, 256>>>(w1, gwb + 0,     32);
    prep_w<<<(32 * 1160 + 255) / 256, 256>>>(w2, gwb + 18944, 128);
    prep_w<<<(32 * 1160 + 255) / 256, 256>>>(w3, gwb + 93184, 128);

    // x -> NHWC fp16 (32 ch)
    transpose_x<<<dim3(2048, 8), 256>>>(x, gx);

    dim3 cg(2, 64, 8);   // 4 output rows per CTA
    conv_mma<32, false><<<cg, 256, 39744>>>(gx, gwb + 0, nullptr, gc);

    scan_all<<<dim3(256, 4), 256>>>(gc, ga, i1w, i1b);

    conv_mma<128, false><<<cg, 256, 144960>>>(ga, gwb + 18944, nullptr, gc);

    scan_all<<<dim3(256, 4), 256>>>(gc, ga, i2w, i2b);

    conv_mma<128, true><<<cg, 256, 144960>>>(ga, gwb + 93184, wo, outp);
}

// round 13
// speedup vs baseline: 2.4215x; 1.0610x over previous
#include <cuda_runtime.h>
#include <cuda_fp16.h>
#include <math.h>
#include <stdint.h>

#define HW 65536

// ---------------------------------------------------------------------------
// Scratch (no allocations allowed)
// ---------------------------------------------------------------------------
__device__ __half g_c16[8ULL * 65536 * 32];    //  32 MB NHWC fp16 conv outputs
__device__ __half g_x16[8ULL * 65536 * 32];    //  32 MB NHWC fp16 x (conv1 input)
__device__ __half g_a16[8ULL * 65536 * 128];   // 128 MB NHWC fp16 irnn outputs
__device__ __align__(16) char g_wb[167424];    // prepped B fp16 (padded row-major)
// conv1: @0 (18944, BSTR=592) ; conv2: @18944 (74240, BSTR=2320) ; conv3: @93184

// ---------------------------------------------------------------------------
__device__ __forceinline__ uint32_t smem_u32(const void* p) {
    uint32_t a;
    asm("{ .reg .u64 t; cvta.to.shared.u64 t, %1; cvt.u32.u64 %0, t; }" : "=r"(a) : "l"(p));
    return a;
}
__device__ __forceinline__ void ldm4(uint32_t* r, uint32_t a) {
    asm volatile("ldmatrix.sync.aligned.m8n8.x4.shared.b16 {%0,%1,%2,%3}, [%4];"
                 : "=r"(r[0]), "=r"(r[1]), "=r"(r[2]), "=r"(r[3]) : "r"(a));
}
__device__ __forceinline__ void mma16816(float* c, const uint32_t* a, uint32_t b0, uint32_t b1) {
    asm volatile("mma.sync.aligned.m16n8k16.row.col.f32.f16.f16.f32 "
        "{%0,%1,%2,%3}, {%4,%5,%6,%7}, {%8,%9}, {%0,%1,%2,%3};"
        : "+f"(c[0]), "+f"(c[1]), "+f"(c[2]), "+f"(c[3])
        : "r"(a[0]), "r"(a[1]), "r"(a[2]), "r"(a[3]), "r"(b0), "r"(b1));
}
__device__ __forceinline__ void cp16(uint32_t saddr, const void* gaddr, int sz) {
    asm volatile("cp.async.cg.shared.global [%0], [%1], 16, %2;"
                 :: "r"(saddr), "l"(gaddr), "r"(sz));
}
__device__ __forceinline__ void cp_commit() { asm volatile("cp.async.commit_group;"); }
__device__ __forceinline__ void cp_wait0()  { asm volatile("cp.async.wait_group 0;"); }
__device__ __forceinline__ void cp_wait1()  { asm volatile("cp.async.wait_group 1;"); }

// ---------------------------------------------------------------------------
// Weight prep: fp32 [32][CIN][3][3] -> fp16 padded row-major B image.
// ---------------------------------------------------------------------------
__global__ void prep_w(const float* __restrict__ w, char* __restrict__ bimg, int CIN)
{
    int K = 9 * CIN, KP = K + 8, BSTR = K * 2 + 16;
    int idx = blockIdx.x * 256 + threadIdx.x;
    if (idx >= 32 * KP) return;
    int n = idx / KP, k = idx - n * KP;
    float v = 0.f;
    if (k < K) {
        int dyi = k / (3 * CIN);
        int r   = k - dyi * 3 * CIN;
        int dxi = r / CIN;
        int c   = r - dxi * CIN;
        v = w[(n * CIN + c) * 9 + dyi * 3 + dxi];
    }
    *(__half*)(bimg + n * BSTR + k * 2) = __float2half(v);
}

// ---------------------------------------------------------------------------
// x (NCHW fp32) -> NHWC fp16 (32 ch)
// ---------------------------------------------------------------------------
__global__ __launch_bounds__(256)
void transpose_x(const float* __restrict__ x, __half* __restrict__ o16)
{
    __shared__ float t[32][33];
    int b = blockIdx.y;
    int p0 = blockIdx.x * 32;
    int lane = threadIdx.x & 31, grp = threadIdx.x >> 5;
#pragma unroll
    for (int i = 0; i < 4; i++) {
        int c = grp + i * 8;
        t[c][lane] = x[((size_t)b * 32 + c) * HW + p0 + lane];
    }
    __syncthreads();
#pragma unroll
    for (int i = 0; i < 4; i++) {
        int p = grp + i * 8;
        o16[((size_t)b * HW + p0 + p) * 32 + lane] = __float2half(t[lane][p]);
    }
}

// ---------------------------------------------------------------------------
// HMMA implicit-GEMM 3x3 conv, 4 output rows/CTA, 8 warps, double-buffered A.
// A fp16; B fp16.  acc += A*B.  Non-FUSE output: fp16 NHWC.
// smem: [B BBYT][A buf0 ABYT][A buf1 ABYT]
// ---------------------------------------------------------------------------
template<int CIN, bool FUSE>
__global__ __launch_bounds__(256, 1)
void conv_mma(const __half* __restrict__ a16, const char* __restrict__ wb,
              const float* __restrict__ wout, void* __restrict__ outv)
{
    constexpr int K     = 9 * CIN;
    constexpr int ASTR  = CIN * 2 + 16;        // A row stride (bytes)
    constexpr int BSTR  = K * 2 + 16;          // B row stride (bytes)
    constexpr int BBYT  = 32 * BSTR;           // B image
    constexpr int V4    = CIN / 8;             // uint4 per pixel-row
    constexpr int ABYT  = 130 * ASTR;          // one staged input row

    extern __shared__ __align__(16) char smem[];
    const int tid  = threadIdx.x;
    const int lane = tid & 31;
    const int wid  = tid >> 5;
    const int w0   = blockIdx.x << 7;
    const int h0   = blockIdx.y << 2;          // first of 4 output rows
    const int b    = blockIdx.z;

    const uint32_t s0  = smem_u32(smem);
    const uint32_t sB  = s0;
    const uint32_t sA0 = s0 + BBYT;

    // group 0: B copy
    {
        const int n4 = BBYT / 16;
        for (int i = tid; i < n4; i += 256)
            cp16(sB + i * 16, wb + i * 16, 16);
        cp_commit();
    }

    // prefetch A input row for stage s into buffer s&1 (always commits a group)
    auto prefetch = [&](int s) {
        const int ir = h0 - 1 + s;
        const uint32_t abase = sA0 + (uint32_t)(s & 1) * ABYT;
        if ((unsigned)ir < 256u) {
            const size_t rowbase = ((size_t)b * HW + (size_t)ir * 256);
            for (int i = tid; i < 130 * V4; i += 256) {
                int px = i / V4, v = i - px * V4;
                int w  = w0 - 1 + px;
                int ok = ((unsigned)w < 256u);
                int wc = ok ? w : 0;
                cp16(abase + (uint32_t)(px * ASTR + v * 16),
                     (const char*)(a16 + (rowbase + wc) * CIN) + v * 16, ok ? 16 : 0);
            }
        }
        cp_commit();
    };
    prefetch(0);

    const int m0 = wid * 16;
    const uint32_t aRowOff = (uint32_t)(lane & 15) * ASTR + ((lane & 16) ? 16u : 0u);
    const uint32_t bLM = (uint32_t)((lane & 7) + ((lane & 16) ? 8 : 0)) * BSTR
                       + (uint32_t)((lane >> 3) & 1) * 16;

    float acc[4][16];
#pragma unroll
    for (int r = 0; r < 4; r++)
#pragma unroll
        for (int i = 0; i < 16; i++) acc[r][i] = 0.f;

    for (int s = 0; s < 6; s++) {
        const int ir = h0 - 1 + s;
        __syncthreads();                        // done reading buffer (s+1)&1
        if (s < 5) prefetch(s + 1);
        if (s < 5) cp_wait1(); else cp_wait0(); // prefetch(s) (and B) complete
        __syncthreads();
        if ((unsigned)ir >= 256u) continue;

        const uint32_t sA = sA0 + (uint32_t)(s & 1) * ABYT;

#pragma unroll
        for (int dx = 0; dx < 3; dx++) {
#pragma unroll
            for (int kc = 0; kc < CIN / 16; kc++) {
                uint32_t a[4];
                ldm4(a, sA + (uint32_t)(m0 + dx) * ASTR + kc * 32 + aRowOff);
#pragma unroll
                for (int r = 0; r < 4; r++) {
                    const int dy = s - r;
                    if (dy < 0 || dy > 2) continue;
                    const uint32_t kb = (uint32_t)(dy * 3 * CIN + dx * CIN + kc * 16) * 2;
                    uint32_t bh[4], bh2[4];
                    ldm4(bh,  sB + bLM + kb);
                    ldm4(bh2, sB + bLM + kb + 16 * BSTR);
                    float* a0 = acc[r];
                    mma16816(a0 + 0,  a, bh[0],  bh[1]);
                    mma16816(a0 + 4,  a, bh[2],  bh[3]);
                    mma16816(a0 + 8,  a, bh2[0], bh2[1]);
                    mma16816(a0 + 12, a, bh2[2], bh2[3]);
                }
            }
        }
    }

    // epilogue (4 rows)
    const int prow = m0 + (lane >> 2);
#pragma unroll
    for (int r = 0; r < 4; r++) {
        const int h = h0 + r;
        if (!FUSE) {
            __half* ob = (__half*)outv + ((size_t)b * HW + (size_t)h * 256 + w0) * 32;
#pragma unroll
            for (int nt = 0; nt < 4; nt++) {
                int ch = nt * 8 + (lane & 3) * 2;
                *(__half2*)(ob + (size_t)prow * 32 + ch) =
                    __floats2half2_rn(acc[r][nt * 4 + 0], acc[r][nt * 4 + 1]);
                *(__half2*)(ob + (size_t)(prow + 8) * 32 + ch) =
                    __floats2half2_rn(acc[r][nt * 4 + 2], acc[r][nt * 4 + 3]);
            }
        } else {
            float s0v = 0.f, s1v = 0.f;
#pragma unroll
            for (int nt = 0; nt < 4; nt++) {
                int ch = nt * 8 + (lane & 3) * 2;
                float wa = __ldg(&wout[ch]), wb2 = __ldg(&wout[ch + 1]);
                s0v += fmaxf(acc[r][nt * 4 + 0], 0.f) * wa + fmaxf(acc[r][nt * 4 + 1], 0.f) * wb2;
                s1v += fmaxf(acc[r][nt * 4 + 2], 0.f) * wa + fmaxf(acc[r][nt * 4 + 3], 0.f) * wb2;
            }
            s0v += __shfl_xor_sync(0xffffffffu, s0v, 1);
            s0v += __shfl_xor_sync(0xffffffffu, s0v, 2);
            s1v += __shfl_xor_sync(0xffffffffu, s1v, 1);
            s1v += __shfl_xor_sync(0xffffffffu, s1v, 2);
            if ((lane & 3) == 0) {
                float* outp = (float*)outv;
                size_t ob = (size_t)b * HW + (size_t)h * 256 + w0;
                outp[ob + prow]     = 1.0f / (1.0f + expf(-s0v));
                outp[ob + prow + 8] = 1.0f / (1.0f + expf(-s1v));
            }
        }
    }
}

// ---------------------------------------------------------------------------
// IRNN: all 4 directional scans in ONE kernel (blockIdx.y = direction).
// Each thread owns a CHANNEL PAIR (__half2): two independent recurrences,
// half the threads (1 wave), half the loads/stores, ILP-2 on the fma chain.
// ---------------------------------------------------------------------------
template<bool REV>
__device__ __forceinline__
void scan_h_body(const __half* __restrict__ in, __half* __restrict__ o16,
                 float wc0, float bc0, float wc1, float bc1, int c, int ch_off)
{
    int t = blockIdx.x * 256 + threadIdx.x;      // over B*W*16 = 32768
    int w = (t >> 4) & 255, b = t >> 12;
    const __half2* ip = (const __half2*)(in + (size_t)b * HW * 32 + (size_t)w * 32 + c);
    __half2* op = (__half2*)(o16 + (size_t)b * HW * 128 + (size_t)w * 128 + ch_off + c);

    __half2 v0 = REV ? ip[(size_t)255 * 4096] : ip[0];
    float h0 = __low2float(v0), h1 = __high2float(v0);
    op[(size_t)(REV ? 255 : 0) * 16384] = v0;
#pragma unroll 8
    for (int i = 1; i < 256; i++) {
        int y = REV ? (255 - i) : i;
        __half2 v = ip[(size_t)y * 4096];
        h0 = fmaxf(wc0 * h0 + (bc0 + __low2float(v)),  0.f);
        h1 = fmaxf(wc1 * h1 + (bc1 + __high2float(v)), 0.f);
        op[(size_t)y * 16384] = __floats2half2_rn(h0, h1);
    }
}

template<bool REV>
__device__ __forceinline__
void scan_w_body(const __half* __restrict__ in, __half* __restrict__ o16,
                 float wc0, float bc0, float wc1, float bc1, int c, int ch_off)
{
    int t = blockIdx.x * 256 + threadIdx.x;      // over B*H*16 = 32768
    int h = (t >> 4) & 255, b = t >> 12;
    const __half2* ip = (const __half2*)(in + (size_t)b * HW * 32 + (size_t)h * 8192 + c);
    __half2* op = (__half2*)(o16 + (size_t)b * HW * 128 + (size_t)h * 32768 + ch_off + c);

    __half2 v0 = REV ? ip[255 * 16] : ip[0];
    float h0 = __low2float(v0), h1 = __high2float(v0);
    op[(size_t)(REV ? 255 : 0) * 64] = v0;
#pragma unroll 8
    for (int i = 1; i < 256; i++) {
        int w = REV ? (255 - i) : i;
        __half2 v = ip[w * 16];
        h0 = fmaxf(wc0 * h0 + (bc0 + __low2float(v)),  0.f);
        h1 = fmaxf(wc1 * h1 + (bc1 + __high2float(v)), 0.f);
        op[(size_t)w * 64] = __floats2half2_rn(h0, h1);
    }
}

__global__ __launch_bounds__(256)
void scan_all(const __half* __restrict__ in, __half* __restrict__ o16,
              const float* __restrict__ ws, const float* __restrict__ bs)
{
    const int d = blockIdx.y;
    const int c = (threadIdx.x & 15) * 2;        // channel pair base
    const float wc0 = ws[d * 32 + c],     bc0 = bs[d * 32 + c];
    const float wc1 = ws[d * 32 + c + 1], bc1 = bs[d * 32 + c + 1];
    if      (d == 0) scan_h_body<true >(in, o16, wc0, bc0, wc1, bc1, c, 0);    // up
    else if (d == 1) scan_w_body<false>(in, o16, wc0, bc0, wc1, bc1, c, 32);   // right
    else if (d == 2) scan_h_body<false>(in, o16, wc0, bc0, wc1, bc1, c, 64);   // down
    else             scan_w_body<true >(in, o16, wc0, bc0, wc1, bc1, c, 96);   // left
}

// ---------------------------------------------------------------------------
extern "C" void kernel_launch(void* const* d_in, const int* in_sizes, int n_in,
                              void* d_out, int out_size)
{
    const float* x   = (const float*)d_in[0];
    const float* w1  = (const float*)d_in[1];
    const float* w2  = (const float*)d_in[2];
    const float* w3  = (const float*)d_in[3];
    const float* wo  = (const float*)d_in[4];
    const float* i1w = (const float*)d_in[5];
    const float* i1b = (const float*)d_in[6];
    const float* i2w = (const float*)d_in[7];
    const float* i2b = (const float*)d_in[8];
    float* outp = (float*)d_out;

    __half *gc, *gx, *ga;  char* gwb;
    cudaGetSymbolAddress((void**)&gc,  g_c16);
    cudaGetSymbolAddress((void**)&gx,  g_x16);
    cudaGetSymbolAddress((void**)&ga,  g_a16);
    cudaGetSymbolAddress((void**)&gwb, g_wb);

    // smem: conv1 = 18944 + 2*10400 = 39744 ; conv2/3 = 74240 + 2*35360 = 144960
    cudaFuncSetAttribute(conv_mma<32,  false>, cudaFuncAttributeMaxDynamicSharedMemorySize, 39744);
    cudaFuncSetAttribute(conv_mma<128, false>, cudaFuncAttributeMaxDynamicSharedMemorySize, 144960);
    cudaFuncSetAttribute(conv_mma<128, true >, cudaFuncAttributeMaxDynamicSharedMemorySize, 144960);

    // prep B weight images (fp16)
    prep_w<<<(32 * 296  + 255) / 256, 256>>>(w1, gwb + 0,     32);
    prep_w<<<(32 * 1160 + 255) / 256, 256>>>(w2, gwb + 18944, 128);
    prep_w<<<(32 * 1160 + 255) / 256, 256>>>(w3, gwb + 93184, 128);

    // x -> NHWC fp16 (32 ch)
    transpose_x<<<dim3(2048, 8), 256>>>(x, gx);

    dim3 cg(2, 64, 8);   // 4 output rows per CTA
    conv_mma<32, false><<<cg, 256, 39744>>>(gx, gwb + 0, nullptr, gc);

    scan_all<<<dim3(128, 4), 256>>>(gc, ga, i1w, i1b);

    conv_mma<128, false><<<cg, 256, 144960>>>(ga, gwb + 18944, nullptr, gc);

    scan_all<<<dim3(128, 4), 256>>>(gc, ga, i2w, i2b);

    conv_mma<128, true><<<cg, 256, 144960>>>(ga, gwb + 93184, wo, outp);
}

// round 14
// speedup vs baseline: 2.4444x; 1.0095x over previous
#include <cuda_runtime.h>
#include <cuda_fp16.h>
#include <math.h>
#include <stdint.h>

#define HW 65536
#define PLANE 16777216ULL   /* 8 * 65536 * 32 halves = one direction plane */

// ---------------------------------------------------------------------------
// Scratch (no allocations allowed)
// ---------------------------------------------------------------------------
__device__ __half g_c16[8ULL * 65536 * 32];    //  32 MB NHWC fp16 conv outputs
__device__ __half g_x16[8ULL * 65536 * 32];    //  32 MB NHWC fp16 x (conv1 input)
__device__ __half g_a16[4ULL * 8 * 65536 * 32];// 128 MB direction-major irnn outputs
__device__ __align__(16) char g_wb[167424];    // prepped B fp16 (padded row-major)
// conv1: @0 (18944, BSTR=592) ; conv2: @18944 (74240, BSTR=2320) ; conv3: @93184

// ---------------------------------------------------------------------------
__device__ __forceinline__ uint32_t smem_u32(const void* p) {
    uint32_t a;
    asm("{ .reg .u64 t; cvta.to.shared.u64 t, %1; cvt.u32.u64 %0, t; }" : "=r"(a) : "l"(p));
    return a;
}
__device__ __forceinline__ void ldm4(uint32_t* r, uint32_t a) {
    asm volatile("ldmatrix.sync.aligned.m8n8.x4.shared.b16 {%0,%1,%2,%3}, [%4];"
                 : "=r"(r[0]), "=r"(r[1]), "=r"(r[2]), "=r"(r[3]) : "r"(a));
}
__device__ __forceinline__ void mma16816(float* c, const uint32_t* a, uint32_t b0, uint32_t b1) {
    asm volatile("mma.sync.aligned.m16n8k16.row.col.f32.f16.f16.f32 "
        "{%0,%1,%2,%3}, {%4,%5,%6,%7}, {%8,%9}, {%0,%1,%2,%3};"
        : "+f"(c[0]), "+f"(c[1]), "+f"(c[2]), "+f"(c[3])
        : "r"(a[0]), "r"(a[1]), "r"(a[2]), "r"(a[3]), "r"(b0), "r"(b1));
}
__device__ __forceinline__ void cp16(uint32_t saddr, const void* gaddr, int sz) {
    asm volatile("cp.async.cg.shared.global [%0], [%1], 16, %2;"
                 :: "r"(saddr), "l"(gaddr), "r"(sz));
}
__device__ __forceinline__ void cp_commit() { asm volatile("cp.async.commit_group;"); }
__device__ __forceinline__ void cp_wait0()  { asm volatile("cp.async.wait_group 0;"); }
__device__ __forceinline__ void cp_wait1()  { asm volatile("cp.async.wait_group 1;"); }

// ---------------------------------------------------------------------------
// Weight prep: fp32 [32][CIN][3][3] -> fp16 padded row-major B image.
// K order: k = dy*3*CIN + dx*CIN + c, with c = dir*32 + ch for CIN=128.
// ---------------------------------------------------------------------------
__global__ void prep_w(const float* __restrict__ w, char* __restrict__ bimg, int CIN)
{
    int K = 9 * CIN, KP = K + 8, BSTR = K * 2 + 16;
    int idx = blockIdx.x * 256 + threadIdx.x;
    if (idx >= 32 * KP) return;
    int n = idx / KP, k = idx - n * KP;
    float v = 0.f;
    if (k < K) {
        int dyi = k / (3 * CIN);
        int r   = k - dyi * 3 * CIN;
        int dxi = r / CIN;
        int c   = r - dxi * CIN;
        v = w[(n * CIN + c) * 9 + dyi * 3 + dxi];
    }
    *(__half*)(bimg + n * BSTR + k * 2) = __float2half(v);
}

// ---------------------------------------------------------------------------
// x (NCHW fp32) -> NHWC fp16 (32 ch)
// ---------------------------------------------------------------------------
__global__ __launch_bounds__(256)
void transpose_x(const float* __restrict__ x, __half* __restrict__ o16)
{
    __shared__ float t[32][33];
    int b = blockIdx.y;
    int p0 = blockIdx.x * 32;
    int lane = threadIdx.x & 31, grp = threadIdx.x >> 5;
#pragma unroll
    for (int i = 0; i < 4; i++) {
        int c = grp + i * 8;
        t[c][lane] = x[((size_t)b * 32 + c) * HW + p0 + lane];
    }
    __syncthreads();
#pragma unroll
    for (int i = 0; i < 4; i++) {
        int p = grp + i * 8;
        o16[((size_t)b * HW + p0 + p) * 32 + lane] = __float2half(t[lane][p]);
    }
}

// ---------------------------------------------------------------------------
// HMMA implicit-GEMM 3x3 conv, 4 output rows/CTA, 8 warps, double-buffered A.
// A fp16 (CIN=32: one plane; CIN=128: four direction planes gathered);
// B fp16.  Non-FUSE output: fp16 NHWC (32 ch).
// smem: [B BBYT][A buf0 ABYT][A buf1 ABYT]
// ---------------------------------------------------------------------------
template<int CIN, bool FUSE>
__global__ __launch_bounds__(256, 1)
void conv_mma(const __half* __restrict__ a16, const char* __restrict__ wb,
              const float* __restrict__ wout, void* __restrict__ outv)
{
    constexpr int K     = 9 * CIN;
    constexpr int ASTR  = CIN * 2 + 16;        // A row stride (bytes)
    constexpr int BSTR  = K * 2 + 16;          // B row stride (bytes)
    constexpr int BBYT  = 32 * BSTR;           // B image
    constexpr int V4    = CIN / 8;             // uint4 per pixel-row
    constexpr int ABYT  = 130 * ASTR;          // one staged input row

    extern __shared__ __align__(16) char smem[];
    const int tid  = threadIdx.x;
    const int lane = tid & 31;
    const int wid  = tid >> 5;
    const int w0   = blockIdx.x << 7;
    const int h0   = blockIdx.y << 2;          // first of 4 output rows
    const int b    = blockIdx.z;

    const uint32_t s0  = smem_u32(smem);
    const uint32_t sB  = s0;
    const uint32_t sA0 = s0 + BBYT;

    // group 0: B copy
    {
        const int n4 = BBYT / 16;
        for (int i = tid; i < n4; i += 256)
            cp16(sB + i * 16, wb + i * 16, 16);
        cp_commit();
    }

    // prefetch A input row for stage s into buffer s&1 (always commits a group)
    auto prefetch = [&](int s) {
        const int ir = h0 - 1 + s;
        const uint32_t abase = sA0 + (uint32_t)(s & 1) * ABYT;
        if ((unsigned)ir < 256u) {
            const size_t rowbase = ((size_t)b * HW + (size_t)ir * 256);
            for (int i = tid; i < 130 * V4; i += 256) {
                int px = i / V4, v = i - px * V4;
                int w  = w0 - 1 + px;
                int ok = ((unsigned)w < 256u);
                int wc = ok ? w : 0;
                const __half* src;
                if (CIN == 128) {
                    int plane = v >> 2;                 // 32 ch per direction plane
                    src = a16 + (size_t)plane * PLANE + (rowbase + wc) * 32 + (v & 3) * 8;
                } else {
                    src = a16 + (rowbase + wc) * 32 + v * 8;
                }
                cp16(abase + (uint32_t)(px * ASTR + v * 16), src, ok ? 16 : 0);
            }
        }
        cp_commit();
    };
    prefetch(0);

    const int m0 = wid * 16;
    const uint32_t aRowOff = (uint32_t)(lane & 15) * ASTR + ((lane & 16) ? 16u : 0u);
    const uint32_t bLM = (uint32_t)((lane & 7) + ((lane & 16) ? 8 : 0)) * BSTR
                       + (uint32_t)((lane >> 3) & 1) * 16;

    float acc[4][16];
#pragma unroll
    for (int r = 0; r < 4; r++)
#pragma unroll
        for (int i = 0; i < 16; i++) acc[r][i] = 0.f;

    for (int s = 0; s < 6; s++) {
        const int ir = h0 - 1 + s;
        __syncthreads();                        // done reading buffer (s+1)&1
        if (s < 5) prefetch(s + 1);
        if (s < 5) cp_wait1(); else cp_wait0(); // prefetch(s) (and B) complete
        __syncthreads();
        if ((unsigned)ir >= 256u) continue;

        const uint32_t sA = sA0 + (uint32_t)(s & 1) * ABYT;

#pragma unroll
        for (int dx = 0; dx < 3; dx++) {
#pragma unroll
            for (int kc = 0; kc < CIN / 16; kc++) {
                uint32_t a[4];
                ldm4(a, sA + (uint32_t)(m0 + dx) * ASTR + kc * 32 + aRowOff);
#pragma unroll
                for (int r = 0; r < 4; r++) {
                    const int dy = s - r;
                    if (dy < 0 || dy > 2) continue;
                    const uint32_t kb = (uint32_t)(dy * 3 * CIN + dx * CIN + kc * 16) * 2;
                    uint32_t bh[4], bh2[4];
                    ldm4(bh,  sB + bLM + kb);
                    ldm4(bh2, sB + bLM + kb + 16 * BSTR);
                    float* a0 = acc[r];
                    mma16816(a0 + 0,  a, bh[0],  bh[1]);
                    mma16816(a0 + 4,  a, bh[2],  bh[3]);
                    mma16816(a0 + 8,  a, bh2[0], bh2[1]);
                    mma16816(a0 + 12, a, bh2[2], bh2[3]);
                }
            }
        }
    }

    // epilogue (4 rows)
    const int prow = m0 + (lane >> 2);
#pragma unroll
    for (int r = 0; r < 4; r++) {
        const int h = h0 + r;
        if (!FUSE) {
            __half* ob = (__half*)outv + ((size_t)b * HW + (size_t)h * 256 + w0) * 32;
#pragma unroll
            for (int nt = 0; nt < 4; nt++) {
                int ch = nt * 8 + (lane & 3) * 2;
                *(__half2*)(ob + (size_t)prow * 32 + ch) =
                    __floats2half2_rn(acc[r][nt * 4 + 0], acc[r][nt * 4 + 1]);
                *(__half2*)(ob + (size_t)(prow + 8) * 32 + ch) =
                    __floats2half2_rn(acc[r][nt * 4 + 2], acc[r][nt * 4 + 3]);
            }
        } else {
            float s0v = 0.f, s1v = 0.f;
#pragma unroll
            for (int nt = 0; nt < 4; nt++) {
                int ch = nt * 8 + (lane & 3) * 2;
                float wa = __ldg(&wout[ch]), wb2 = __ldg(&wout[ch + 1]);
                s0v += fmaxf(acc[r][nt * 4 + 0], 0.f) * wa + fmaxf(acc[r][nt * 4 + 1], 0.f) * wb2;
                s1v += fmaxf(acc[r][nt * 4 + 2], 0.f) * wa + fmaxf(acc[r][nt * 4 + 3], 0.f) * wb2;
            }
            s0v += __shfl_xor_sync(0xffffffffu, s0v, 1);
            s0v += __shfl_xor_sync(0xffffffffu, s0v, 2);
            s1v += __shfl_xor_sync(0xffffffffu, s1v, 1);
            s1v += __shfl_xor_sync(0xffffffffu, s1v, 2);
            if ((lane & 3) == 0) {
                float* outp = (float*)outv;
                size_t ob = (size_t)b * HW + (size_t)h * 256 + w0;
                outp[ob + prow]     = 1.0f / (1.0f + expf(-s0v));
                outp[ob + prow + 8] = 1.0f / (1.0f + expf(-s1v));
            }
        }
    }
}

// ---------------------------------------------------------------------------
// IRNN: all 4 directional scans in ONE kernel (blockIdx.y = direction).
// Thread owns a channel pair.  Output: direction-major plane [B][HW][32] —
// warps write fully-coalesced 128B lines.
// ---------------------------------------------------------------------------
template<bool REV>
__device__ __forceinline__
void scan_h_body(const __half* __restrict__ in, __half* __restrict__ plane,
                 float wc0, float bc0, float wc1, float bc1, int c)
{
    int t = blockIdx.x * 256 + threadIdx.x;      // over B*W*16 = 32768
    int w = (t >> 4) & 255, b = t >> 12;
    const __half2* ip = (const __half2*)(in + (size_t)b * HW * 32 + (size_t)w * 32 + c);
    __half2* op = (__half2*)(plane + ((size_t)b * HW + w) * 32 + c);

    __half2 v0 = REV ? ip[(size_t)255 * 4096] : ip[0];
    float h0 = __low2float(v0), h1 = __high2float(v0);
    op[(size_t)(REV ? 255 : 0) * 4096] = v0;
#pragma unroll 8
    for (int i = 1; i < 256; i++) {
        int y = REV ? (255 - i) : i;
        __half2 v = ip[(size_t)y * 4096];
        h0 = fmaxf(wc0 * h0 + (bc0 + __low2float(v)),  0.f);
        h1 = fmaxf(wc1 * h1 + (bc1 + __high2float(v)), 0.f);
        op[(size_t)y * 4096] = __floats2half2_rn(h0, h1);
    }
}

template<bool REV>
__device__ __forceinline__
void scan_w_body(const __half* __restrict__ in, __half* __restrict__ plane,
                 float wc0, float bc0, float wc1, float bc1, int c)
{
    int t = blockIdx.x * 256 + threadIdx.x;      // over B*H*16 = 32768
    int h = (t >> 4) & 255, b = t >> 12;
    const __half2* ip = (const __half2*)(in + (size_t)b * HW * 32 + (size_t)h * 8192 + c);
    __half2* op = (__half2*)(plane + ((size_t)b * HW + (size_t)h * 256) * 32 + c);

    __half2 v0 = REV ? ip[255 * 16] : ip[0];
    float h0 = __low2float(v0), h1 = __high2float(v0);
    op[(size_t)(REV ? 255 : 0) * 16] = v0;
#pragma unroll 8
    for (int i = 1; i < 256; i++) {
        int w = REV ? (255 - i) : i;
        __half2 v = ip[w * 16];
        h0 = fmaxf(wc0 * h0 + (bc0 + __low2float(v)),  0.f);
        h1 = fmaxf(wc1 * h1 + (bc1 + __high2float(v)), 0.f);
        op[(size_t)w * 16] = __floats2half2_rn(h0, h1);
    }
}

__global__ __launch_bounds__(256)
void scan_all(const __half* __restrict__ in, __half* __restrict__ o16,
              const float* __restrict__ ws, const float* __restrict__ bs)
{
    const int d = blockIdx.y;
    const int c = (threadIdx.x & 15) * 2;        // channel pair base
    const float wc0 = ws[d * 32 + c],     bc0 = bs[d * 32 + c];
    const float wc1 = ws[d * 32 + c + 1], bc1 = bs[d * 32 + c + 1];
    __half* plane = o16 + (size_t)d * PLANE;
    if      (d == 0) scan_h_body<true >(in, plane, wc0, bc0, wc1, bc1, c);   // up
    else if (d == 1) scan_w_body<false>(in, plane, wc0, bc0, wc1, bc1, c);   // right
    else if (d == 2) scan_h_body<false>(in, plane, wc0, bc0, wc1, bc1, c);   // down
    else             scan_w_body<true >(in, plane, wc0, bc0, wc1, bc1, c);   // left
}

// ---------------------------------------------------------------------------
extern "C" void kernel_launch(void* const* d_in, const int* in_sizes, int n_in,
                              void* d_out, int out_size)
{
    const float* x   = (const float*)d_in[0];
    const float* w1  = (const float*)d_in[1];
    const float* w2  = (const float*)d_in[2];
    const float* w3  = (const float*)d_in[3];
    const float* wo  = (const float*)d_in[4];
    const float* i1w = (const float*)d_in[5];
    const float* i1b = (const float*)d_in[6];
    const float* i2w = (const float*)d_in[7];
    const float* i2b = (const float*)d_in[8];
    float* outp = (float*)d_out;

    __half *gc, *gx, *ga;  char* gwb;
    cudaGetSymbolAddress((void**)&gc,  g_c16);
    cudaGetSymbolAddress((void**)&gx,  g_x16);
    cudaGetSymbolAddress((void**)&ga,  g_a16);
    cudaGetSymbolAddress((void**)&gwb, g_wb);

    // smem: conv1 = 18944 + 2*10400 = 39744 ; conv2/3 = 74240 + 2*35360 = 144960
    cudaFuncSetAttribute(conv_mma<32,  false>, cudaFuncAttributeMaxDynamicSharedMemorySize, 39744);
    cudaFuncSetAttribute(conv_mma<128, false>, cudaFuncAttributeMaxDynamicSharedMemorySize, 144960);
    cudaFuncSetAttribute(conv_mma<128, true >, cudaFuncAttributeMaxDynamicSharedMemorySize, 144960);

    // prep B weight images (fp16)
    prep_w<<<(32 * 296  + 255) / 256, 256>>>(w1, gwb + 0,     32);
    prep_w<<<(32 * 1160 + 255) / 256, 256>>>(w2, gwb + 18944, 128);
    prep_w<<<(32 * 1160 + 255) / 256, 256>>>(w3, gwb + 93184, 128);

    // x -> NHWC fp16 (32 ch)
    transpose_x<<<dim3(2048, 8), 256>>>(x, gx);

    dim3 cg(2, 64, 8);   // 4 output rows per CTA
    conv_mma<32, false><<<cg, 256, 39744>>>(gx, gwb + 0, nullptr, gc);

    scan_all<<<dim3(128, 4), 256>>>(gc, ga, i1w, i1b);

    conv_mma<128, false><<<cg, 256, 144960>>>(ga, gwb + 18944, nullptr, gc);

    scan_all<<<dim3(128, 4), 256>>>(gc, ga, i2w, i2b);

    conv_mma<128, true><<<cg, 256, 144960>>>(ga, gwb + 93184, wo, outp);
}